// round 1
// baseline (speedup 1.0000x reference)
#include <cuda_runtime.h>

#define NMAX 50000
#define EMAX 500000

// Scratch (static device globals -- no allocation allowed)
__device__ float g_P[(size_t)NMAX * 768];   // cols 0-255: W1*x, 256-511: W2*x, 512-767: Wagg*x + b_agg
__device__ float g_attn[(size_t)EMAX * 8];  // logits -> exp -> beta
__device__ float g_segmax[NMAX * 8];
__device__ float g_segsum[NMAX * 8];

__device__ __forceinline__ void atomicMaxFloat(float* addr, float val) {
    if (val >= 0.0f) atomicMax((int*)addr, __float_as_int(val));
    else             atomicMin((unsigned int*)addr, __float_as_uint(val));
}

__device__ __forceinline__ void red_add_v4(float* p, float a, float b, float c, float d) {
    asm volatile("red.global.add.v4.f32 [%0], {%1,%2,%3,%4};"
                 :: "l"(p), "f"(a), "f"(b), "f"(c), "f"(d) : "memory");
}

// ---------------------------------------------------------------------------
// init: zero out, segsum; segmax = -inf
// ---------------------------------------------------------------------------
__global__ void init_kernel(float4* __restrict__ out4, int n4, int n8) {
    int i = blockIdx.x * blockDim.x + threadIdx.x;
    if (i < n4) out4[i] = make_float4(0.f, 0.f, 0.f, 0.f);
    if (i < n8) {
        g_segmax[i] = __int_as_float(0xff800000);  // -inf
        g_segsum[i] = 0.f;
    }
}

// ---------------------------------------------------------------------------
// Fused per-node GEMM: P[N,768] = emb[N,256] @ Wt[256,768]
//   cols   0-255 : attn_proj_w[:, 0:256]^T
//   cols 256-511 : attn_proj_w[:, 256:512]^T
//   cols 512-767 : aggr_proj_w^T  (+ aggr_proj_b)
// 64x64 tile, BK=16, 256 threads, 4x4 register tile per thread.
// ---------------------------------------------------------------------------
__global__ void gemm_kernel(const float* __restrict__ emb,
                            const float* __restrict__ attn_w,   // (256, 512) row-major
                            const float* __restrict__ aggr_w,   // (256, 256) row-major
                            const float* __restrict__ aggr_b,   // (256)
                            int Nn)
{
    __shared__ float As[16][68];
    __shared__ float Bs[16][68];

    const int m0    = blockIdx.x * 64;
    const int jbase = blockIdx.y * 64;

    const float* Bptr;
    int ldb;
    if (jbase < 256)      { Bptr = attn_w + (size_t)jbase * 512;               ldb = 512; }
    else if (jbase < 512) { Bptr = attn_w + (size_t)(jbase - 256) * 512 + 256; ldb = 512; }
    else                  { Bptr = aggr_w + (size_t)(jbase - 512) * 256;       ldb = 256; }

    const int tid  = threadIdx.x;
    const int tx   = tid & 15;
    const int ty   = tid >> 4;
    const int lRow = tid >> 2;         // 0..63
    const int lK   = (tid & 3) << 2;   // 0,4,8,12

    float acc[4][4];
    #pragma unroll
    for (int i = 0; i < 4; i++)
        #pragma unroll
        for (int j = 0; j < 4; j++) acc[i][j] = 0.f;

    for (int k0 = 0; k0 < 256; k0 += 16) {
        int gm = m0 + lRow;
        float4 a4 = make_float4(0.f, 0.f, 0.f, 0.f);
        if (gm < Nn) a4 = *(const float4*)&emb[(size_t)gm * 256 + k0 + lK];
        As[lK + 0][lRow] = a4.x;
        As[lK + 1][lRow] = a4.y;
        As[lK + 2][lRow] = a4.z;
        As[lK + 3][lRow] = a4.w;

        float4 b4 = *(const float4*)&Bptr[(size_t)lRow * ldb + k0 + lK];
        Bs[lK + 0][lRow] = b4.x;
        Bs[lK + 1][lRow] = b4.y;
        Bs[lK + 2][lRow] = b4.z;
        Bs[lK + 3][lRow] = b4.w;
        __syncthreads();

        #pragma unroll
        for (int k = 0; k < 16; k++) {
            float4 av = *(const float4*)&As[k][ty * 4];
            float4 bv = *(const float4*)&Bs[k][tx * 4];
            float ar[4] = {av.x, av.y, av.z, av.w};
            float br[4] = {bv.x, bv.y, bv.z, bv.w};
            #pragma unroll
            for (int i = 0; i < 4; i++)
                #pragma unroll
                for (int j = 0; j < 4; j++)
                    acc[i][j] += ar[i] * br[j];
        }
        __syncthreads();
    }

    float bias[4] = {0.f, 0.f, 0.f, 0.f};
    if (jbase >= 512) {
        #pragma unroll
        for (int j = 0; j < 4; j++) bias[j] = aggr_b[jbase - 512 + tx * 4 + j];
    }
    #pragma unroll
    for (int i = 0; i < 4; i++) {
        int gm = m0 + ty * 4 + i;
        if (gm < Nn) {
            float4 v;
            v.x = acc[i][0] + bias[0];
            v.y = acc[i][1] + bias[1];
            v.z = acc[i][2] + bias[2];
            v.w = acc[i][3] + bias[3];
            *(float4*)&g_P[(size_t)gm * 768 + jbase + tx * 4] = v;
        }
    }
}

// ---------------------------------------------------------------------------
// Per-edge attention logits: one warp per edge.
// lane l handles dims [8l, 8l+8) (all inside head l/4).
// logit[e,h] = sum_d lrelu(P1[head,d]+P2[tail,d]+b[d]) * av[d] + attn_bin[bin,h]
// Also atomicMax into segmax.
// ---------------------------------------------------------------------------
__global__ void edge_logit_kernel(const int* __restrict__ head,
                                  const int* __restrict__ tail,
                                  const int* __restrict__ bins,
                                  const float* __restrict__ proj_b,   // 256
                                  const float* __restrict__ attn_vec, // 256 (H*DH)
                                  const float* __restrict__ attn_bin, // 10*8
                                  int E)
{
    __shared__ float sb[256];
    __shared__ float sav[256];
    for (int i = threadIdx.x; i < 256; i += blockDim.x) {
        sb[i]  = proj_b[i];
        sav[i] = attn_vec[i];
    }
    __syncthreads();

    int gw   = (blockIdx.x * blockDim.x + threadIdx.x) >> 5;
    int lane = threadIdx.x & 31;
    if (gw >= E) return;

    int hd = head[gw];
    int tl = tail[gw];
    const float* p1 = g_P + (size_t)hd * 768;
    const float* p2 = g_P + (size_t)tl * 768 + 256;

    int d0 = lane * 8;
    float s = 0.f;
    #pragma unroll
    for (int q = 0; q < 2; q++) {
        int d = d0 + q * 4;
        float4 x = *(const float4*)&p1[d];
        float4 y = *(const float4*)&p2[d];
        float v;
        v = x.x + y.x + sb[d + 0]; v = v >= 0.f ? v : 0.2f * v; s += v * sav[d + 0];
        v = x.y + y.y + sb[d + 1]; v = v >= 0.f ? v : 0.2f * v; s += v * sav[d + 1];
        v = x.z + y.z + sb[d + 2]; v = v >= 0.f ? v : 0.2f * v; s += v * sav[d + 2];
        v = x.w + y.w + sb[d + 3]; v = v >= 0.f ? v : 0.2f * v; s += v * sav[d + 3];
    }
    // reduce within groups of 4 lanes (one head each)
    s += __shfl_xor_sync(0xffffffffu, s, 1);
    s += __shfl_xor_sync(0xffffffffu, s, 2);

    if ((lane & 3) == 0) {
        int h = lane >> 2;
        float raw = s + attn_bin[bins[gw] * 8 + h];
        g_attn[(size_t)gw * 8 + h] = raw;
        atomicMaxFloat(&g_segmax[hd * 8 + h], raw);
    }
}

// ---------------------------------------------------------------------------
// exp(raw - segmax[head]) and segment sum
// ---------------------------------------------------------------------------
__global__ void edge_exp_kernel(const int* __restrict__ head, int E8) {
    int i = blockIdx.x * blockDim.x + threadIdx.x;
    if (i >= E8) return;
    int hd = head[i >> 3];
    int h  = i & 7;
    float ev = __expf(g_attn[i] - g_segmax[hd * 8 + h]);
    g_attn[i] = ev;
    atomicAdd(&g_segsum[hd * 8 + h], ev);
}

// ---------------------------------------------------------------------------
// beta = exp / (segsum + 1e-16), in place
// ---------------------------------------------------------------------------
__global__ void beta_kernel(const int* __restrict__ head, int E8) {
    int i = blockIdx.x * blockDim.x + threadIdx.x;
    if (i >= E8) return;
    int hd = head[i >> 3];
    g_attn[i] = g_attn[i] / (g_segsum[hd * 8 + (i & 7)] + 1e-16f);
}

// ---------------------------------------------------------------------------
// scatter: out[head] += beta[e,h] * A[tail], one warp per edge,
// vector red.global.add.v4.f32 (16B per atomic op)
// ---------------------------------------------------------------------------
__global__ void scatter_kernel(const int* __restrict__ head,
                               const int* __restrict__ tail,
                               float* __restrict__ out, int E)
{
    int gw   = (blockIdx.x * blockDim.x + threadIdx.x) >> 5;
    int lane = threadIdx.x & 31;
    if (gw >= E) return;

    int hd = head[gw];
    int tl = tail[gw];
    const float* A = g_P + (size_t)tl * 768 + 512;
    float* o = out + (size_t)hd * 256;

    #pragma unroll
    for (int q = 0; q < 2; q++) {
        int d = q * 128 + lane * 4;
        int h = d >> 5;
        float beta = g_attn[(size_t)gw * 8 + h];
        float4 a = *(const float4*)&A[d];
        red_add_v4(&o[d], beta * a.x, beta * a.y, beta * a.z, beta * a.w);
    }
}

// ---------------------------------------------------------------------------
extern "C" void kernel_launch(void* const* d_in, const int* in_sizes, int n_in,
                              void* d_out, int out_size)
{
    const float* emb      = (const float*)d_in[0];
    const int*   head     = (const int*)  d_in[1];
    const int*   tail     = (const int*)  d_in[2];
    const int*   bins     = (const int*)  d_in[3];
    const float* attn_w   = (const float*)d_in[4];
    const float* proj_b   = (const float*)d_in[5];
    const float* attn_bin = (const float*)d_in[6];
    const float* attn_vec = (const float*)d_in[7];
    const float* aggr_w   = (const float*)d_in[8];
    const float* aggr_b   = (const float*)d_in[9];
    float* out = (float*)d_out;

    int Nn = in_sizes[0] / 256;
    int E  = in_sizes[1];

    int n4 = Nn * 64;  // float4 count of out
    int n8 = Nn * 8;
    init_kernel<<<(n4 + 255) / 256, 256>>>((float4*)out, n4, n8);

    dim3 ggrid((Nn + 63) / 64, 12);
    gemm_kernel<<<ggrid, 256>>>(emb, attn_w, aggr_w, aggr_b, Nn);

    int blocksE = (E + 7) / 8;  // 8 warps (edges) per 256-thread block
    edge_logit_kernel<<<blocksE, 256>>>(head, tail, bins, proj_b, attn_vec, attn_bin, E);

    int E8 = E * 8;
    edge_exp_kernel<<<(E8 + 255) / 256, 256>>>(head, E8);
    beta_kernel<<<(E8 + 255) / 256, 256>>>(head, E8);

    scatter_kernel<<<blocksE, 256>>>(head, tail, out, E);
}

// round 2
// speedup vs baseline: 1.6757x; 1.6757x over previous
#include <cuda_runtime.h>
#include <cstdint>

#define NMAX 50000
#define EMAX 500000

// Scratch (static device globals -- no allocation allowed)
__device__ float g_P[(size_t)NMAX * 768];   // cols 0-255: W1*x, 256-511: W2*x, 512-767: Wagg*x + b_agg
__device__ float g_attn[(size_t)EMAX * 8];  // logits -> exp
__device__ float g_segmax[NMAX * 8];
__device__ float g_segsum[NMAX * 8];

__device__ __forceinline__ void atomicMaxFloat(float* addr, float val) {
    if (val >= 0.0f) atomicMax((int*)addr, __float_as_int(val));
    else             atomicMin((unsigned int*)addr, __float_as_uint(val));
}

__device__ __forceinline__ void red_add_v4(float* p, float a, float b, float c, float d) {
    asm volatile("red.global.add.v4.f32 [%0], {%1,%2,%3,%4};"
                 :: "l"(p), "f"(a), "f"(b), "f"(c), "f"(d) : "memory");
}

__device__ __forceinline__ float to_tf32(float x) {
    float r;
    asm("cvt.rna.tf32.f32 %0, %1;" : "=f"(r) : "f"(x));
    return r;
}

// ---------------------------------------------------------------------------
// init: zero out, segsum; segmax = -inf
// ---------------------------------------------------------------------------
__global__ void init_kernel(float4* __restrict__ out4, int n4, int n8) {
    int i = blockIdx.x * blockDim.x + threadIdx.x;
    if (i < n4) out4[i] = make_float4(0.f, 0.f, 0.f, 0.f);
    if (i < n8) {
        g_segmax[i] = __int_as_float(0xff800000);  // -inf
        g_segsum[i] = 0.f;
    }
}

// ---------------------------------------------------------------------------
// Fused per-node GEMM (tf32 tensor cores):
//   P[N,768] = emb[N,256] @ Wt[256,768]
//   cols   0-255 : attn_proj_w[:, 0:256]^T
//   cols 256-511 : attn_proj_w[:, 256:512]^T
//   cols 512-767 : aggr_proj_w^T  (+ aggr_proj_b)
// Block tile 128x64, BK=32, 256 threads = 8 warps (4 x 2), warp tile 32x32,
// mma.sync.m16n8k8.tf32.
// ---------------------------------------------------------------------------
#define BM 128
#define BN 64
#define BK 32
#define PAD 4

__global__ void gemm_tf32_kernel(const float* __restrict__ emb,
                                 const float* __restrict__ attn_w,   // (256, 512) row-major
                                 const float* __restrict__ aggr_w,   // (256, 256) row-major
                                 const float* __restrict__ aggr_b,   // (256)
                                 int Nn)
{
    __shared__ float As[BM][BK + PAD];
    __shared__ float Bs[BN][BK + PAD];

    const int m0    = blockIdx.x * BM;
    const int jbase = blockIdx.y * BN;

    const float* Bptr;
    int ldb;
    if (jbase < 256)      { Bptr = attn_w + (size_t)jbase * 512;               ldb = 512; }
    else if (jbase < 512) { Bptr = attn_w + (size_t)(jbase - 256) * 512 + 256; ldb = 512; }
    else                  { Bptr = aggr_w + (size_t)(jbase - 512) * 256;       ldb = 256; }

    const int tid  = threadIdx.x;
    const int lane = tid & 31;
    const int wid  = tid >> 5;
    const int wm   = wid >> 1;    // 0..3 -> rows [wm*32, +32)
    const int wn   = wid & 1;     // 0..1 -> cols [wn*32, +32)

    float acc[2][4][4];
    #pragma unroll
    for (int i = 0; i < 2; i++)
        #pragma unroll
        for (int j = 0; j < 4; j++)
            #pragma unroll
            for (int k = 0; k < 4; k++) acc[i][j][k] = 0.f;

    const int qrow = lane >> 2;   // 0..7
    const int qcol = lane & 3;    // 0..3

    for (int k0 = 0; k0 < 256; k0 += BK) {
        // global loads: A 128x32 (4 float4/thread), B 64x32 (2 float4/thread)
        float4 areg[4];
        #pragma unroll
        for (int t = 0; t < 4; t++) {
            int idx = tid + t * 256;         // 0..1023
            int row = idx >> 3;              // 0..127
            int c4  = (idx & 7) << 2;        // 0,4,...,28
            int gm  = m0 + row;
            float4 v = make_float4(0.f, 0.f, 0.f, 0.f);
            if (gm < Nn) v = *(const float4*)&emb[(size_t)gm * 256 + k0 + c4];
            areg[t] = v;
        }
        float4 breg[2];
        #pragma unroll
        for (int t = 0; t < 2; t++) {
            int idx = tid + t * 256;         // 0..511
            int row = idx >> 3;              // 0..63
            int c4  = (idx & 7) << 2;
            breg[t] = *(const float4*)&Bptr[(size_t)row * ldb + k0 + c4];
        }

        __syncthreads();   // previous compute done

        #pragma unroll
        for (int t = 0; t < 4; t++) {
            int idx = tid + t * 256;
            int row = idx >> 3;
            int c4  = (idx & 7) << 2;
            As[row][c4 + 0] = to_tf32(areg[t].x);
            As[row][c4 + 1] = to_tf32(areg[t].y);
            As[row][c4 + 2] = to_tf32(areg[t].z);
            As[row][c4 + 3] = to_tf32(areg[t].w);
        }
        #pragma unroll
        for (int t = 0; t < 2; t++) {
            int idx = tid + t * 256;
            int row = idx >> 3;
            int c4  = (idx & 7) << 2;
            Bs[row][c4 + 0] = to_tf32(breg[t].x);
            Bs[row][c4 + 1] = to_tf32(breg[t].y);
            Bs[row][c4 + 2] = to_tf32(breg[t].z);
            Bs[row][c4 + 3] = to_tf32(breg[t].w);
        }

        __syncthreads();

        #pragma unroll
        for (int ks = 0; ks < BK / 8; ks++) {
            const int c = ks * 8 + qcol;
            uint32_t a[2][4];
            #pragma unroll
            for (int mf = 0; mf < 2; mf++) {
                int r = wm * 32 + mf * 16 + qrow;
                a[mf][0] = __float_as_uint(As[r][c]);
                a[mf][1] = __float_as_uint(As[r + 8][c]);
                a[mf][2] = __float_as_uint(As[r][c + 4]);
                a[mf][3] = __float_as_uint(As[r + 8][c + 4]);
            }
            uint32_t b[4][2];
            #pragma unroll
            for (int nf = 0; nf < 4; nf++) {
                int n = wn * 32 + nf * 8 + qrow;
                b[nf][0] = __float_as_uint(Bs[n][c]);
                b[nf][1] = __float_as_uint(Bs[n][c + 4]);
            }
            #pragma unroll
            for (int mf = 0; mf < 2; mf++)
                #pragma unroll
                for (int nf = 0; nf < 4; nf++) {
                    asm volatile(
                        "mma.sync.aligned.m16n8k8.row.col.f32.tf32.tf32.f32 "
                        "{%0,%1,%2,%3}, {%4,%5,%6,%7}, {%8,%9}, {%0,%1,%2,%3};"
                        : "+f"(acc[mf][nf][0]), "+f"(acc[mf][nf][1]),
                          "+f"(acc[mf][nf][2]), "+f"(acc[mf][nf][3])
                        : "r"(a[mf][0]), "r"(a[mf][1]), "r"(a[mf][2]), "r"(a[mf][3]),
                          "r"(b[nf][0]), "r"(b[nf][1]));
                }
        }
        __syncthreads();
    }

    // epilogue: acc[mf][nf][{d0,d1,d2,d3}]:
    //   d0,d1 -> row r,   cols 2*qcol, 2*qcol+1
    //   d2,d3 -> row r+8
    const bool has_bias = (jbase >= 512);
    #pragma unroll
    for (int mf = 0; mf < 2; mf++) {
        #pragma unroll
        for (int nf = 0; nf < 4; nf++) {
            int gc = jbase + wn * 32 + nf * 8 + 2 * qcol;
            float b0 = 0.f, b1 = 0.f;
            if (has_bias) {
                b0 = aggr_b[gc - 512];
                b1 = aggr_b[gc - 511];
            }
            int gr0 = m0 + wm * 32 + mf * 16 + qrow;
            int gr1 = gr0 + 8;
            if (gr0 < Nn) {
                float2 v = make_float2(acc[mf][nf][0] + b0, acc[mf][nf][1] + b1);
                *(float2*)&g_P[(size_t)gr0 * 768 + gc] = v;
            }
            if (gr1 < Nn) {
                float2 v = make_float2(acc[mf][nf][2] + b0, acc[mf][nf][3] + b1);
                *(float2*)&g_P[(size_t)gr1 * 768 + gc] = v;
            }
        }
    }
}

// ---------------------------------------------------------------------------
// Per-edge attention logits: one warp per edge.
// lane l handles dims [8l, 8l+8) (all inside head l/4).
// logit[e,h] = sum_d lrelu(P1[head,d]+P2[tail,d]+b[d]) * av[d] + attn_bin[bin,h]
// Also atomicMax into segmax.
// ---------------------------------------------------------------------------
__global__ void edge_logit_kernel(const int* __restrict__ head,
                                  const int* __restrict__ tail,
                                  const int* __restrict__ bins,
                                  const float* __restrict__ proj_b,   // 256
                                  const float* __restrict__ attn_vec, // 256 (H*DH)
                                  const float* __restrict__ attn_bin, // 10*8
                                  int E)
{
    __shared__ float sb[256];
    __shared__ float sav[256];
    for (int i = threadIdx.x; i < 256; i += blockDim.x) {
        sb[i]  = proj_b[i];
        sav[i] = attn_vec[i];
    }
    __syncthreads();

    int gw   = (blockIdx.x * blockDim.x + threadIdx.x) >> 5;
    int lane = threadIdx.x & 31;
    if (gw >= E) return;

    int hd = head[gw];
    int tl = tail[gw];
    const float* p1 = g_P + (size_t)hd * 768;
    const float* p2 = g_P + (size_t)tl * 768 + 256;

    int d0 = lane * 8;
    float s = 0.f;
    #pragma unroll
    for (int q = 0; q < 2; q++) {
        int d = d0 + q * 4;
        float4 x = *(const float4*)&p1[d];
        float4 y = *(const float4*)&p2[d];
        float v;
        v = x.x + y.x + sb[d + 0]; v = v >= 0.f ? v : 0.2f * v; s += v * sav[d + 0];
        v = x.y + y.y + sb[d + 1]; v = v >= 0.f ? v : 0.2f * v; s += v * sav[d + 1];
        v = x.z + y.z + sb[d + 2]; v = v >= 0.f ? v : 0.2f * v; s += v * sav[d + 2];
        v = x.w + y.w + sb[d + 3]; v = v >= 0.f ? v : 0.2f * v; s += v * sav[d + 3];
    }
    // reduce within groups of 4 lanes (one head each)
    s += __shfl_xor_sync(0xffffffffu, s, 1);
    s += __shfl_xor_sync(0xffffffffu, s, 2);

    if ((lane & 3) == 0) {
        int h = lane >> 2;
        float raw = s + attn_bin[bins[gw] * 8 + h];
        g_attn[(size_t)gw * 8 + h] = raw;
        atomicMaxFloat(&g_segmax[hd * 8 + h], raw);
    }
}

// ---------------------------------------------------------------------------
// exp(raw - segmax[head]) and segment sum; 2 threads per edge, float4 each
// ---------------------------------------------------------------------------
__global__ void edge_exp_kernel(const int* __restrict__ head, int E2) {
    int i = blockIdx.x * blockDim.x + threadIdx.x;
    if (i >= E2) return;
    int e    = i >> 1;
    int half = (i & 1) << 2;
    int hd   = head[e];
    float4 v = *(const float4*)&g_attn[(size_t)e * 8 + half];
    float4 m = *(const float4*)&g_segmax[hd * 8 + half];
    v.x = __expf(v.x - m.x);
    v.y = __expf(v.y - m.y);
    v.z = __expf(v.z - m.z);
    v.w = __expf(v.w - m.w);
    *(float4*)&g_attn[(size_t)e * 8 + half] = v;
    float* ss = &g_segsum[hd * 8 + half];
    atomicAdd(&ss[0], v.x);
    atomicAdd(&ss[1], v.y);
    atomicAdd(&ss[2], v.z);
    atomicAdd(&ss[3], v.w);
}

// ---------------------------------------------------------------------------
// scatter: out[head] += beta[e,h] * A[tail], one warp per edge.
// beta computed in-warp (lanes 0-7) and shuffle-broadcast; vector red.v4.
// ---------------------------------------------------------------------------
__global__ void scatter_kernel(const int* __restrict__ head,
                               const int* __restrict__ tail,
                               float* __restrict__ out, int E)
{
    int gw   = (blockIdx.x * blockDim.x + threadIdx.x) >> 5;
    int lane = threadIdx.x & 31;
    if (gw >= E) return;

    int hd = head[gw];
    int tl = tail[gw];

    float beta_l = 0.f;
    if (lane < 8)
        beta_l = g_attn[(size_t)gw * 8 + lane] / (g_segsum[hd * 8 + lane] + 1e-16f);

    const float* A = g_P + (size_t)tl * 768 + 512;
    float* o = out + (size_t)hd * 256;

    #pragma unroll
    for (int q = 0; q < 2; q++) {
        int d = q * 128 + lane * 4;
        int h = d >> 5;
        float beta = __shfl_sync(0xffffffffu, beta_l, h);
        float4 a = *(const float4*)&A[d];
        red_add_v4(&o[d], beta * a.x, beta * a.y, beta * a.z, beta * a.w);
    }
}

// ---------------------------------------------------------------------------
extern "C" void kernel_launch(void* const* d_in, const int* in_sizes, int n_in,
                              void* d_out, int out_size)
{
    const float* emb      = (const float*)d_in[0];
    const int*   head     = (const int*)  d_in[1];
    const int*   tail     = (const int*)  d_in[2];
    const int*   bins     = (const int*)  d_in[3];
    const float* attn_w   = (const float*)d_in[4];
    const float* proj_b   = (const float*)d_in[5];
    const float* attn_bin = (const float*)d_in[6];
    const float* attn_vec = (const float*)d_in[7];
    const float* aggr_w   = (const float*)d_in[8];
    const float* aggr_b   = (const float*)d_in[9];
    float* out = (float*)d_out;

    int Nn = in_sizes[0] / 256;
    int E  = in_sizes[1];

    int n4 = Nn * 64;  // float4 count of out
    int n8 = Nn * 8;
    init_kernel<<<(n4 + 255) / 256, 256>>>((float4*)out, n4, n8);

    dim3 ggrid((Nn + BM - 1) / BM, 768 / BN);
    gemm_tf32_kernel<<<ggrid, 256>>>(emb, attn_w, aggr_w, aggr_b, Nn);

    int blocksE = (E + 7) / 8;  // 8 warps (edges) per 256-thread block
    edge_logit_kernel<<<blocksE, 256>>>(head, tail, bins, proj_b, attn_vec, attn_bin, E);

    int E2 = E * 2;
    edge_exp_kernel<<<(E2 + 255) / 256, 256>>>(head, E2);

    scatter_kernel<<<blocksE, 256>>>(head, tail, out, E);
}

// round 3
// speedup vs baseline: 1.7339x; 1.0347x over previous
#include <cuda_runtime.h>
#include <cuda_fp16.h>
#include <cstdint>

#define NMAX 50000
#define EMAX 500000

// Scratch (static device globals -- no allocation allowed)
__device__ __half g_P12h[(size_t)NMAX * 512]; // cols 0-255: W1*x + b, 256-511: W2*x   (fp16)
__device__ float  g_A[(size_t)NMAX * 256];    // Wagg*x + b_agg (fp32)
__device__ float  g_attn[(size_t)EMAX * 8];   // logits -> exp
__device__ float  g_segmax[NMAX * 8];
__device__ float  g_segsum[NMAX * 8];

__device__ __forceinline__ void atomicMaxFloat(float* addr, float val) {
    if (val >= 0.0f) atomicMax((int*)addr, __float_as_int(val));
    else             atomicMin((unsigned int*)addr, __float_as_uint(val));
}

__device__ __forceinline__ void red_add_v4(float* p, float a, float b, float c, float d) {
    asm volatile("red.global.add.v4.f32 [%0], {%1,%2,%3,%4};"
                 :: "l"(p), "f"(a), "f"(b), "f"(c), "f"(d) : "memory");
}

__device__ __forceinline__ float to_tf32(float x) {
    float r;
    asm("cvt.rna.tf32.f32 %0, %1;" : "=f"(r) : "f"(x));
    return r;
}

// ---------------------------------------------------------------------------
// init: zero out, segsum; segmax = -inf
// ---------------------------------------------------------------------------
__global__ void init_kernel(float4* __restrict__ out4, int n4, int n8) {
    int i = blockIdx.x * blockDim.x + threadIdx.x;
    if (i < n4) out4[i] = make_float4(0.f, 0.f, 0.f, 0.f);
    if (i < n8) {
        g_segmax[i] = __int_as_float(0xff800000);  // -inf
        g_segsum[i] = 0.f;
    }
}

// ---------------------------------------------------------------------------
// Fused per-node GEMM (tf32 tensor cores):
//   cols   0-255 : attn_proj_w[:, 0:256]^T @ emb + proj_b  -> g_P12h[:, 0:256]   (fp16)
//   cols 256-511 : attn_proj_w[:, 256:512]^T @ emb          -> g_P12h[:, 256:512] (fp16)
//   cols 512-767 : aggr_proj_w^T @ emb + aggr_b             -> g_A               (fp32)
// Block tile 128x64, BK=32, 256 threads = 8 warps (4 x 2), warp tile 32x32.
// ---------------------------------------------------------------------------
#define BM 128
#define BN 64
#define BK 32
#define PAD 4

__global__ void gemm_tf32_kernel(const float* __restrict__ emb,
                                 const float* __restrict__ attn_w,   // (256, 512) row-major
                                 const float* __restrict__ aggr_w,   // (256, 256) row-major
                                 const float* __restrict__ proj_b,   // (256)
                                 const float* __restrict__ aggr_b,   // (256)
                                 int Nn)
{
    __shared__ float As[BM][BK + PAD];
    __shared__ float Bs[BN][BK + PAD];

    const int m0    = blockIdx.x * BM;
    const int jbase = blockIdx.y * BN;

    const float* Bptr;
    int ldb;
    if (jbase < 256)      { Bptr = attn_w + (size_t)jbase * 512;               ldb = 512; }
    else if (jbase < 512) { Bptr = attn_w + (size_t)(jbase - 256) * 512 + 256; ldb = 512; }
    else                  { Bptr = aggr_w + (size_t)(jbase - 512) * 256;       ldb = 256; }

    const int tid  = threadIdx.x;
    const int lane = tid & 31;
    const int wid  = tid >> 5;
    const int wm   = wid >> 1;    // 0..3 -> rows [wm*32, +32)
    const int wn   = wid & 1;     // 0..1 -> cols [wn*32, +32)

    float acc[2][4][4];
    #pragma unroll
    for (int i = 0; i < 2; i++)
        #pragma unroll
        for (int j = 0; j < 4; j++)
            #pragma unroll
            for (int k = 0; k < 4; k++) acc[i][j][k] = 0.f;

    const int qrow = lane >> 2;   // 0..7
    const int qcol = lane & 3;    // 0..3

    for (int k0 = 0; k0 < 256; k0 += BK) {
        float4 areg[4];
        #pragma unroll
        for (int t = 0; t < 4; t++) {
            int idx = tid + t * 256;
            int row = idx >> 3;
            int c4  = (idx & 7) << 2;
            int gm  = m0 + row;
            float4 v = make_float4(0.f, 0.f, 0.f, 0.f);
            if (gm < Nn) v = *(const float4*)&emb[(size_t)gm * 256 + k0 + c4];
            areg[t] = v;
        }
        float4 breg[2];
        #pragma unroll
        for (int t = 0; t < 2; t++) {
            int idx = tid + t * 256;
            int row = idx >> 3;
            int c4  = (idx & 7) << 2;
            breg[t] = *(const float4*)&Bptr[(size_t)row * ldb + k0 + c4];
        }

        __syncthreads();

        #pragma unroll
        for (int t = 0; t < 4; t++) {
            int idx = tid + t * 256;
            int row = idx >> 3;
            int c4  = (idx & 7) << 2;
            As[row][c4 + 0] = to_tf32(areg[t].x);
            As[row][c4 + 1] = to_tf32(areg[t].y);
            As[row][c4 + 2] = to_tf32(areg[t].z);
            As[row][c4 + 3] = to_tf32(areg[t].w);
        }
        #pragma unroll
        for (int t = 0; t < 2; t++) {
            int idx = tid + t * 256;
            int row = idx >> 3;
            int c4  = (idx & 7) << 2;
            Bs[row][c4 + 0] = to_tf32(breg[t].x);
            Bs[row][c4 + 1] = to_tf32(breg[t].y);
            Bs[row][c4 + 2] = to_tf32(breg[t].z);
            Bs[row][c4 + 3] = to_tf32(breg[t].w);
        }

        __syncthreads();

        #pragma unroll
        for (int ks = 0; ks < BK / 8; ks++) {
            const int c = ks * 8 + qcol;
            uint32_t a[2][4];
            #pragma unroll
            for (int mf = 0; mf < 2; mf++) {
                int r = wm * 32 + mf * 16 + qrow;
                a[mf][0] = __float_as_uint(As[r][c]);
                a[mf][1] = __float_as_uint(As[r + 8][c]);
                a[mf][2] = __float_as_uint(As[r][c + 4]);
                a[mf][3] = __float_as_uint(As[r + 8][c + 4]);
            }
            uint32_t b[4][2];
            #pragma unroll
            for (int nf = 0; nf < 4; nf++) {
                int n = wn * 32 + nf * 8 + qrow;
                b[nf][0] = __float_as_uint(Bs[n][c]);
                b[nf][1] = __float_as_uint(Bs[n][c + 4]);
            }
            #pragma unroll
            for (int mf = 0; mf < 2; mf++)
                #pragma unroll
                for (int nf = 0; nf < 4; nf++) {
                    asm volatile(
                        "mma.sync.aligned.m16n8k8.row.col.f32.tf32.tf32.f32 "
                        "{%0,%1,%2,%3}, {%4,%5,%6,%7}, {%8,%9}, {%0,%1,%2,%3};"
                        : "+f"(acc[mf][nf][0]), "+f"(acc[mf][nf][1]),
                          "+f"(acc[mf][nf][2]), "+f"(acc[mf][nf][3])
                        : "r"(a[mf][0]), "r"(a[mf][1]), "r"(a[mf][2]), "r"(a[mf][3]),
                          "r"(b[nf][0]), "r"(b[nf][1]));
                }
        }
        __syncthreads();
    }

    // epilogue
    #pragma unroll
    for (int mf = 0; mf < 2; mf++) {
        #pragma unroll
        for (int nf = 0; nf < 4; nf++) {
            int gc = jbase + wn * 32 + nf * 8 + 2 * qcol;
            int gr0 = m0 + wm * 32 + mf * 16 + qrow;
            int gr1 = gr0 + 8;
            if (gc < 256) {
                // P1 + proj_b -> fp16
                float b0 = proj_b[gc], b1 = proj_b[gc + 1];
                if (gr0 < Nn)
                    *(__half2*)&g_P12h[(size_t)gr0 * 512 + gc] =
                        __floats2half2_rn(acc[mf][nf][0] + b0, acc[mf][nf][1] + b1);
                if (gr1 < Nn)
                    *(__half2*)&g_P12h[(size_t)gr1 * 512 + gc] =
                        __floats2half2_rn(acc[mf][nf][2] + b0, acc[mf][nf][3] + b1);
            } else if (gc < 512) {
                // P2 -> fp16
                if (gr0 < Nn)
                    *(__half2*)&g_P12h[(size_t)gr0 * 512 + gc] =
                        __floats2half2_rn(acc[mf][nf][0], acc[mf][nf][1]);
                if (gr1 < Nn)
                    *(__half2*)&g_P12h[(size_t)gr1 * 512 + gc] =
                        __floats2half2_rn(acc[mf][nf][2], acc[mf][nf][3]);
            } else {
                // A + aggr_b -> fp32
                float b0 = aggr_b[gc - 512], b1 = aggr_b[gc - 511];
                if (gr0 < Nn)
                    *(float2*)&g_A[(size_t)gr0 * 256 + gc - 512] =
                        make_float2(acc[mf][nf][0] + b0, acc[mf][nf][1] + b1);
                if (gr1 < Nn)
                    *(float2*)&g_A[(size_t)gr1 * 256 + gc - 512] =
                        make_float2(acc[mf][nf][2] + b0, acc[mf][nf][3] + b1);
            }
        }
    }
}

// ---------------------------------------------------------------------------
// Per-edge attention logits: one warp per edge, fp16 gathers.
// lane l handles dims [8l, 8l+8) (all inside head l/4).
// ---------------------------------------------------------------------------
__global__ void edge_logit_kernel(const int* __restrict__ head,
                                  const int* __restrict__ tail,
                                  const int* __restrict__ bins,
                                  const float* __restrict__ attn_vec, // 256 (H*DH)
                                  const float* __restrict__ attn_bin, // 10*8
                                  int E)
{
    __shared__ float sav[256];
    for (int i = threadIdx.x; i < 256; i += blockDim.x)
        sav[i] = attn_vec[i];
    __syncthreads();

    int gw   = (blockIdx.x * blockDim.x + threadIdx.x) >> 5;
    int lane = threadIdx.x & 31;
    if (gw >= E) return;

    int hd = head[gw];
    int tl = tail[gw];
    const __half* p1 = g_P12h + (size_t)hd * 512;
    const __half* p2 = g_P12h + (size_t)tl * 512 + 256;

    int d0 = lane * 8;
    uint4 xu = *(const uint4*)&p1[d0];   // 8 halfs
    uint4 yu = *(const uint4*)&p2[d0];

    float s = 0.f;
    const uint32_t* xp = &xu.x;
    const uint32_t* yp = &yu.x;
    #pragma unroll
    for (int q = 0; q < 4; q++) {
        float2 fx = __half22float2(*(const __half2*)&xp[q]);
        float2 fy = __half22float2(*(const __half2*)&yp[q]);
        int d = d0 + q * 2;
        float v;
        v = fx.x + fy.x; v = v >= 0.f ? v : 0.2f * v; s += v * sav[d + 0];
        v = fx.y + fy.y; v = v >= 0.f ? v : 0.2f * v; s += v * sav[d + 1];
    }
    // reduce within groups of 4 lanes (one head each)
    s += __shfl_xor_sync(0xffffffffu, s, 1);
    s += __shfl_xor_sync(0xffffffffu, s, 2);

    if ((lane & 3) == 0) {
        int h = lane >> 2;
        float raw = s + attn_bin[bins[gw] * 8 + h];
        g_attn[(size_t)gw * 8 + h] = raw;
        atomicMaxFloat(&g_segmax[hd * 8 + h], raw);
    }
}

// ---------------------------------------------------------------------------
// exp(raw - segmax[head]) and segment sum; 2 threads per edge, float4 each
// ---------------------------------------------------------------------------
__global__ void edge_exp_kernel(const int* __restrict__ head, int E2) {
    int i = blockIdx.x * blockDim.x + threadIdx.x;
    if (i >= E2) return;
    int e    = i >> 1;
    int half = (i & 1) << 2;
    int hd   = head[e];
    float4 v = *(const float4*)&g_attn[(size_t)e * 8 + half];
    float4 m = *(const float4*)&g_segmax[hd * 8 + half];
    v.x = __expf(v.x - m.x);
    v.y = __expf(v.y - m.y);
    v.z = __expf(v.z - m.z);
    v.w = __expf(v.w - m.w);
    *(float4*)&g_attn[(size_t)e * 8 + half] = v;
    float* ss = &g_segsum[hd * 8 + half];
    atomicAdd(&ss[0], v.x);
    atomicAdd(&ss[1], v.y);
    atomicAdd(&ss[2], v.z);
    atomicAdd(&ss[3], v.w);
}

// ---------------------------------------------------------------------------
// scatter: out[head] += beta[e,h] * A[tail], one warp per edge.
// beta computed in-warp (lanes 0-7) and shuffle-broadcast; vector red.v4.
// ---------------------------------------------------------------------------
__global__ void scatter_kernel(const int* __restrict__ head,
                               const int* __restrict__ tail,
                               float* __restrict__ out, int E)
{
    int gw   = (blockIdx.x * blockDim.x + threadIdx.x) >> 5;
    int lane = threadIdx.x & 31;
    if (gw >= E) return;

    int hd = head[gw];
    int tl = tail[gw];

    float beta_l = 0.f;
    if (lane < 8)
        beta_l = g_attn[(size_t)gw * 8 + lane] / (g_segsum[hd * 8 + lane] + 1e-16f);

    const float* A = g_A + (size_t)tl * 256;
    float* o = out + (size_t)hd * 256;

    #pragma unroll
    for (int q = 0; q < 2; q++) {
        int d = q * 128 + lane * 4;
        int h = d >> 5;
        float beta = __shfl_sync(0xffffffffu, beta_l, h);
        float4 a = *(const float4*)&A[d];
        red_add_v4(&o[d], beta * a.x, beta * a.y, beta * a.z, beta * a.w);
    }
}

// ---------------------------------------------------------------------------
extern "C" void kernel_launch(void* const* d_in, const int* in_sizes, int n_in,
                              void* d_out, int out_size)
{
    const float* emb      = (const float*)d_in[0];
    const int*   head     = (const int*)  d_in[1];
    const int*   tail     = (const int*)  d_in[2];
    const int*   bins     = (const int*)  d_in[3];
    const float* attn_w   = (const float*)d_in[4];
    const float* proj_b   = (const float*)d_in[5];
    const float* attn_bin = (const float*)d_in[6];
    const float* attn_vec = (const float*)d_in[7];
    const float* aggr_w   = (const float*)d_in[8];
    const float* aggr_b   = (const float*)d_in[9];
    float* out = (float*)d_out;

    int Nn = in_sizes[0] / 256;
    int E  = in_sizes[1];

    int n4 = Nn * 64;  // float4 count of out
    int n8 = Nn * 8;
    init_kernel<<<(n4 + 255) / 256, 256>>>((float4*)out, n4, n8);

    dim3 ggrid((Nn + BM - 1) / BM, 768 / BN);
    gemm_tf32_kernel<<<ggrid, 256>>>(emb, attn_w, aggr_w, proj_b, aggr_b, Nn);

    int blocksE = (E + 7) / 8;  // 8 warps (edges) per 256-thread block
    edge_logit_kernel<<<blocksE, 256>>>(head, tail, bins, attn_vec, attn_bin, E);

    int E2 = E * 2;
    edge_exp_kernel<<<(E2 + 255) / 256, 256>>>(head, E2);

    scatter_kernel<<<blocksE, 256>>>(head, tail, out, E);
}

// round 4
// speedup vs baseline: 2.4508x; 1.4135x over previous
#include <cuda_runtime.h>
#include <cuda_fp16.h>
#include <cstdint>

#define NMAX 50000
#define EMAX 500000

// Scratch (static device globals -- no allocation allowed)
__device__ __half g_Ph[(size_t)NMAX * 768]; // 0-255: W1*x+b (fp16), 256-511: W2*x, 512-767: Wagg*x+b_agg
__device__ int    g_hist[NMAX];
__device__ int    g_cnt[NMAX];
__device__ int    g_offs[NMAX + 1];
__device__ int    g_tail_s[EMAX];
__device__ int    g_bins_s[EMAX];

__device__ __forceinline__ float to_tf32(float x) {
    float r;
    asm("cvt.rna.tf32.f32 %0, %1;" : "=f"(r) : "f"(x));
    return r;
}

// ---------------------------------------------------------------------------
// zero histogram + per-node counters
// ---------------------------------------------------------------------------
__global__ void zero_kernel(int Nn) {
    int i = blockIdx.x * blockDim.x + threadIdx.x;
    if (i < Nn) { g_hist[i] = 0; g_cnt[i] = 0; }
}

// ---------------------------------------------------------------------------
// degree histogram over head node
// ---------------------------------------------------------------------------
__global__ void hist_kernel(const int* __restrict__ head, int E) {
    int e = blockIdx.x * blockDim.x + threadIdx.x;
    if (e < E) atomicAdd(&g_hist[head[e]], 1);
}

// ---------------------------------------------------------------------------
// exclusive scan of g_hist -> g_offs (single block, 1024 threads, warp shuffles)
// ---------------------------------------------------------------------------
__global__ void scan_kernel(int Nn) {
    __shared__ int swarp[32];
    __shared__ int scarry;
    int tid = threadIdx.x, lane = tid & 31, wid = tid >> 5;
    if (tid == 0) scarry = 0;
    __syncthreads();
    for (int base = 0; base < Nn; base += 1024) {
        int i = base + tid;
        int v = (i < Nn) ? g_hist[i] : 0;
        int incl = v;
        #pragma unroll
        for (int off = 1; off < 32; off <<= 1) {
            int t = __shfl_up_sync(0xffffffffu, incl, off);
            if (lane >= off) incl += t;
        }
        if (lane == 31) swarp[wid] = incl;
        __syncthreads();
        if (wid == 0) {
            int wv = swarp[lane];
            int winc = wv;
            #pragma unroll
            for (int off = 1; off < 32; off <<= 1) {
                int t = __shfl_up_sync(0xffffffffu, winc, off);
                if (lane >= off) winc += t;
            }
            swarp[lane] = winc - wv;  // exclusive
        }
        __syncthreads();
        int excl = scarry + swarp[wid] + (incl - v);
        if (i < Nn) g_offs[i] = excl;
        __syncthreads();
        if (tid == 1023) scarry = excl + v;   // new running total
        __syncthreads();
    }
    if (threadIdx.x == 0) g_offs[Nn] = scarry;
}

// ---------------------------------------------------------------------------
// scatter edges into head-sorted order (tail and bin gathered along)
// ---------------------------------------------------------------------------
__global__ void sortscatter_kernel(const int* __restrict__ head,
                                   const int* __restrict__ tail,
                                   const int* __restrict__ bins, int E) {
    int e = blockIdx.x * blockDim.x + threadIdx.x;
    if (e >= E) return;
    int h = head[e];
    int p = g_offs[h] + atomicAdd(&g_cnt[h], 1);
    g_tail_s[p] = tail[e];
    g_bins_s[p] = bins[e];
}

// ---------------------------------------------------------------------------
// Fused per-node GEMM (tf32 tensor cores), prefetched pipeline:
//   g_Ph cols   0-255 : attn_proj_w[:, 0:256]^T @ emb + proj_b   (fp16)
//   g_Ph cols 256-511 : attn_proj_w[:, 256:512]^T @ emb          (fp16)
//   g_Ph cols 512-767 : aggr_proj_w^T @ emb + aggr_b             (fp16)
// Block tile 128x64, BK=32, 256 threads = 8 warps (4x2), warp tile 32x32.
// ---------------------------------------------------------------------------
#define BM 128
#define BN 64
#define BK 32
#define PAD 4

__global__ void gemm_tf32_kernel(const float* __restrict__ emb,
                                 const float* __restrict__ attn_w,   // (256, 512) row-major
                                 const float* __restrict__ aggr_w,   // (256, 256) row-major
                                 const float* __restrict__ proj_b,   // (256)
                                 const float* __restrict__ aggr_b,   // (256)
                                 int Nn)
{
    __shared__ float As[BM][BK + PAD];
    __shared__ float Bs[BN][BK + PAD];

    const int m0    = blockIdx.x * BM;
    const int jbase = blockIdx.y * BN;

    const float* Bptr;
    int ldb;
    if (jbase < 256)      { Bptr = attn_w + (size_t)jbase * 512;               ldb = 512; }
    else if (jbase < 512) { Bptr = attn_w + (size_t)(jbase - 256) * 512 + 256; ldb = 512; }
    else                  { Bptr = aggr_w + (size_t)(jbase - 512) * 256;       ldb = 256; }

    const int tid  = threadIdx.x;
    const int lane = tid & 31;
    const int wid  = tid >> 5;
    const int wm   = wid >> 1;
    const int wn   = wid & 1;

    float acc[2][4][4];
    #pragma unroll
    for (int i = 0; i < 2; i++)
        #pragma unroll
        for (int j = 0; j < 4; j++)
            #pragma unroll
            for (int k = 0; k < 4; k++) acc[i][j][k] = 0.f;

    const int qrow = lane >> 2;
    const int qcol = lane & 3;

    const int arow = tid >> 3;            // for A loads: rows tid/8 (+128/4 step via t)
    const int ac4  = (tid & 7) << 2;

    float4 areg[4];
    float4 breg[2];
    // prologue: load k0 = 0
    #pragma unroll
    for (int t = 0; t < 4; t++) {
        int row = arow + t * 32;
        int gm  = m0 + row;
        float4 v = make_float4(0.f, 0.f, 0.f, 0.f);
        if (gm < Nn) v = *(const float4*)&emb[(size_t)gm * 256 + ac4];
        areg[t] = v;
    }
    #pragma unroll
    for (int t = 0; t < 2; t++) {
        int row = arow + t * 32;
        breg[t] = *(const float4*)&Bptr[(size_t)row * ldb + ac4];
    }

    for (int it = 0; it < 8; it++) {
        __syncthreads();   // previous compute done (no-op cost on it=0)
        #pragma unroll
        for (int t = 0; t < 4; t++) {
            int row = arow + t * 32;
            As[row][ac4 + 0] = to_tf32(areg[t].x);
            As[row][ac4 + 1] = to_tf32(areg[t].y);
            As[row][ac4 + 2] = to_tf32(areg[t].z);
            As[row][ac4 + 3] = to_tf32(areg[t].w);
        }
        #pragma unroll
        for (int t = 0; t < 2; t++) {
            int row = arow + t * 32;
            Bs[row][ac4 + 0] = to_tf32(breg[t].x);
            Bs[row][ac4 + 1] = to_tf32(breg[t].y);
            Bs[row][ac4 + 2] = to_tf32(breg[t].z);
            Bs[row][ac4 + 3] = to_tf32(breg[t].w);
        }
        __syncthreads();

        if (it < 7) {
            int k0 = (it + 1) * BK;
            #pragma unroll
            for (int t = 0; t < 4; t++) {
                int row = arow + t * 32;
                int gm  = m0 + row;
                float4 v = make_float4(0.f, 0.f, 0.f, 0.f);
                if (gm < Nn) v = *(const float4*)&emb[(size_t)gm * 256 + k0 + ac4];
                areg[t] = v;
            }
            #pragma unroll
            for (int t = 0; t < 2; t++) {
                int row = arow + t * 32;
                breg[t] = *(const float4*)&Bptr[(size_t)row * ldb + k0 + ac4];
            }
        }

        #pragma unroll
        for (int ks = 0; ks < BK / 8; ks++) {
            const int c = ks * 8 + qcol;
            uint32_t a[2][4];
            #pragma unroll
            for (int mf = 0; mf < 2; mf++) {
                int r = wm * 32 + mf * 16 + qrow;
                a[mf][0] = __float_as_uint(As[r][c]);
                a[mf][1] = __float_as_uint(As[r + 8][c]);
                a[mf][2] = __float_as_uint(As[r][c + 4]);
                a[mf][3] = __float_as_uint(As[r + 8][c + 4]);
            }
            uint32_t b[4][2];
            #pragma unroll
            for (int nf = 0; nf < 4; nf++) {
                int n = wn * 32 + nf * 8 + qrow;
                b[nf][0] = __float_as_uint(Bs[n][c]);
                b[nf][1] = __float_as_uint(Bs[n][c + 4]);
            }
            #pragma unroll
            for (int mf = 0; mf < 2; mf++)
                #pragma unroll
                for (int nf = 0; nf < 4; nf++) {
                    asm volatile(
                        "mma.sync.aligned.m16n8k8.row.col.f32.tf32.tf32.f32 "
                        "{%0,%1,%2,%3}, {%4,%5,%6,%7}, {%8,%9}, {%0,%1,%2,%3};"
                        : "+f"(acc[mf][nf][0]), "+f"(acc[mf][nf][1]),
                          "+f"(acc[mf][nf][2]), "+f"(acc[mf][nf][3])
                        : "r"(a[mf][0]), "r"(a[mf][1]), "r"(a[mf][2]), "r"(a[mf][3]),
                          "r"(b[nf][0]), "r"(b[nf][1]));
                }
        }
    }

    // epilogue: everything to fp16 g_Ph
    #pragma unroll
    for (int mf = 0; mf < 2; mf++) {
        #pragma unroll
        for (int nf = 0; nf < 4; nf++) {
            int gc = jbase + wn * 32 + nf * 8 + 2 * qcol;
            float b0 = 0.f, b1 = 0.f;
            if (gc < 256)      { b0 = proj_b[gc];       b1 = proj_b[gc + 1]; }
            else if (gc >= 512){ b0 = aggr_b[gc - 512]; b1 = aggr_b[gc - 511]; }
            int gr0 = m0 + wm * 32 + mf * 16 + qrow;
            int gr1 = gr0 + 8;
            if (gr0 < Nn)
                *(__half2*)&g_Ph[(size_t)gr0 * 768 + gc] =
                    __floats2half2_rn(acc[mf][nf][0] + b0, acc[mf][nf][1] + b1);
            if (gr1 < Nn)
                *(__half2*)&g_Ph[(size_t)gr1 * 768 + gc] =
                    __floats2half2_rn(acc[mf][nf][2] + b0, acc[mf][nf][3] + b1);
        }
    }
}

// ---------------------------------------------------------------------------
// Per-node fused attention + aggregation: one warp per head node.
// Online softmax over the node's (head-sorted) edges; no atomics; plain store.
// lane l covers dims [8l, 8l+8), head = l/4.
// ---------------------------------------------------------------------------
__global__ void node_kernel(const float* __restrict__ attn_vec, // 256
                            const float* __restrict__ attn_bin, // 10*8
                            float* __restrict__ out, int Nn)
{
    __shared__ float sav[256];
    __shared__ float sbin[80];
    for (int i = threadIdx.x; i < 256; i += blockDim.x) sav[i] = attn_vec[i];
    for (int i = threadIdx.x; i < 80;  i += blockDim.x) sbin[i] = attn_bin[i];
    __syncthreads();

    int n    = (blockIdx.x * blockDim.x + threadIdx.x) >> 5;
    int lane = threadIdx.x & 31;
    if (n >= Nn) return;

    int beg = g_offs[n];
    int cnt = g_offs[n + 1] - beg;
    const int d0 = lane * 8;
    const int hsel = lane >> 2;

    // P1 row for this node (gathered once)
    uint4 xu = *(const uint4*)(g_Ph + (size_t)n * 768 + d0);

    float m = __int_as_float(0xff800000);  // -inf
    float ssum = 0.f;
    float accv[8];
    #pragma unroll
    for (int q = 0; q < 8; q++) accv[q] = 0.f;

    // prefetch edge 0
    uint4 yu_n = make_uint4(0,0,0,0), au_n = make_uint4(0,0,0,0);
    int bn_n = 0;
    if (cnt > 0) {
        int tl = g_tail_s[beg];
        bn_n = g_bins_s[beg];
        const __half* pr = g_Ph + (size_t)tl * 768;
        yu_n = *(const uint4*)(pr + 256 + d0);
        au_n = *(const uint4*)(pr + 512 + d0);
    }

    for (int i = 0; i < cnt; i++) {
        uint4 yu = yu_n, au = au_n;
        int be = bn_n;
        if (i + 1 < cnt) {
            int tl = g_tail_s[beg + i + 1];
            bn_n = g_bins_s[beg + i + 1];
            const __half* pr = g_Ph + (size_t)tl * 768;
            yu_n = *(const uint4*)(pr + 256 + d0);
            au_n = *(const uint4*)(pr + 512 + d0);
        }

        // logit contribution (8 dims per lane)
        const uint32_t* xp = &xu.x;
        const uint32_t* yp = &yu.x;
        float s = 0.f;
        #pragma unroll
        for (int q = 0; q < 4; q++) {
            float2 fx = __half22float2(*(const __half2*)&xp[q]);
            float2 fy = __half22float2(*(const __half2*)&yp[q]);
            int d = d0 + q * 2;
            float v;
            v = fx.x + fy.x; v = v >= 0.f ? v : 0.2f * v; s += v * sav[d + 0];
            v = fx.y + fy.y; v = v >= 0.f ? v : 0.2f * v; s += v * sav[d + 1];
        }
        s += __shfl_xor_sync(0xffffffffu, s, 1);
        s += __shfl_xor_sync(0xffffffffu, s, 2);   // full head-sum in all 4 lanes of group

        float raw = s + sbin[be * 8 + hsel];

        // online softmax update (per head group; group-uniform values)
        float mn    = fmaxf(m, raw);
        float scale = __expf(m - mn);     // exp(-inf)=0 on first edge
        float ev    = __expf(raw - mn);
        ssum = ssum * scale + ev;
        m = mn;

        const uint32_t* ap = &au.x;
        #pragma unroll
        for (int q = 0; q < 4; q++) {
            float2 fa = __half22float2(*(const __half2*)&ap[q]);
            accv[q * 2 + 0] = accv[q * 2 + 0] * scale + ev * fa.x;
            accv[q * 2 + 1] = accv[q * 2 + 1] * scale + ev * fa.y;
        }
    }

    float inv = 1.f / (ssum + 1e-16f);
    float4 o0 = make_float4(accv[0] * inv, accv[1] * inv, accv[2] * inv, accv[3] * inv);
    float4 o1 = make_float4(accv[4] * inv, accv[5] * inv, accv[6] * inv, accv[7] * inv);
    float* op = out + (size_t)n * 256 + d0;
    *(float4*)op       = o0;
    *(float4*)(op + 4) = o1;
}

// ---------------------------------------------------------------------------
extern "C" void kernel_launch(void* const* d_in, const int* in_sizes, int n_in,
                              void* d_out, int out_size)
{
    const float* emb      = (const float*)d_in[0];
    const int*   head     = (const int*)  d_in[1];
    const int*   tail     = (const int*)  d_in[2];
    const int*   bins     = (const int*)  d_in[3];
    const float* attn_w   = (const float*)d_in[4];
    const float* proj_b   = (const float*)d_in[5];
    const float* attn_bin = (const float*)d_in[6];
    const float* attn_vec = (const float*)d_in[7];
    const float* aggr_w   = (const float*)d_in[8];
    const float* aggr_b   = (const float*)d_in[9];
    float* out = (float*)d_out;

    int Nn = in_sizes[0] / 256;
    int E  = in_sizes[1];

    zero_kernel<<<(Nn + 255) / 256, 256>>>(Nn);

    dim3 ggrid((Nn + BM - 1) / BM, 768 / BN);
    gemm_tf32_kernel<<<ggrid, 256>>>(emb, attn_w, aggr_w, proj_b, aggr_b, Nn);

    hist_kernel<<<(E + 255) / 256, 256>>>(head, E);
    scan_kernel<<<1, 1024>>>(Nn);
    sortscatter_kernel<<<(E + 255) / 256, 256>>>(head, tail, bins, E);

    int warps = Nn;  // one warp per node
    node_kernel<<<(warps * 32 + 255) / 256, 256>>>(attn_vec, attn_bin, out, Nn);
}

// round 5
// speedup vs baseline: 2.7902x; 1.1385x over previous
#include <cuda_runtime.h>
#include <cuda_fp16.h>
#include <cstdint>

#define NMAX 50000
#define EMAX 500000

// Scratch (static device globals -- no allocation allowed)
__device__ __half g_Ph[(size_t)NMAX * 768]; // 0-255: W1*x+b, 256-511: W2*x, 512-767: Wagg*x+b_agg (fp16)
__device__ float  g_embr[(size_t)NMAX * 256]; // tf32-rounded emb
__device__ float  g_W[768 * 256];             // tf32-rounded packed weights (row j = output col j)
__device__ int    g_hist[NMAX];
__device__ int    g_cnt[NMAX];
__device__ int    g_offs[NMAX + 1];
__device__ int    g_bsum[1024];
__device__ int    g_tail_s[EMAX];
__device__ int    g_bins_s[EMAX];

__device__ __forceinline__ float to_tf32(float x) {
    float r;
    asm("cvt.rna.tf32.f32 %0, %1;" : "=f"(r) : "f"(x));
    return r;
}

__device__ __forceinline__ void cp_async16(uint32_t saddr, const void* gptr, int src_size) {
    asm volatile("cp.async.cg.shared.global [%0], [%1], 16, %2;"
                 :: "r"(saddr), "l"(gptr), "r"(src_size));
}
#define CP_COMMIT() asm volatile("cp.async.commit_group;")
#define CP_WAIT0()  asm volatile("cp.async.wait_group 0;")

// ---------------------------------------------------------------------------
// pre-round emb to tf32 (stored as fp32)
// ---------------------------------------------------------------------------
__global__ void round_emb_kernel(const float* __restrict__ emb, int n4) {
    int i = blockIdx.x * blockDim.x + threadIdx.x;
    if (i >= n4) return;
    float4 v = ((const float4*)emb)[i];
    v.x = to_tf32(v.x); v.y = to_tf32(v.y); v.z = to_tf32(v.z); v.w = to_tf32(v.w);
    ((float4*)g_embr)[i] = v;
}

// ---------------------------------------------------------------------------
// pack + round weights: g_W row j (k contiguous):
//   j<256   : attn_proj_w[j, 0:256]
//   256-511 : attn_proj_w[j-256, 256:512]
//   512-767 : aggr_proj_w[j-512, :]
// ---------------------------------------------------------------------------
__global__ void round_w_kernel(const float* __restrict__ attn_w,
                               const float* __restrict__ aggr_w) {
    int i = blockIdx.x * blockDim.x + threadIdx.x;   // 0 .. 768*64-1 (float4)
    if (i >= 768 * 64) return;
    int j  = i >> 6;
    int c4 = (i & 63) << 2;
    const float* src;
    if (j < 256)      src = attn_w + (size_t)j * 512 + c4;
    else if (j < 512) src = attn_w + (size_t)(j - 256) * 512 + 256 + c4;
    else              src = aggr_w + (size_t)(j - 512) * 256 + c4;
    float4 v = *(const float4*)src;
    v.x = to_tf32(v.x); v.y = to_tf32(v.y); v.z = to_tf32(v.z); v.w = to_tf32(v.w);
    *(float4*)&g_W[(size_t)j * 256 + c4] = v;
}

// ---------------------------------------------------------------------------
// zero histogram + per-node counters
// ---------------------------------------------------------------------------
__global__ void zero_kernel(int Nn) {
    int i = blockIdx.x * blockDim.x + threadIdx.x;
    if (i < Nn) { g_hist[i] = 0; g_cnt[i] = 0; }
}

__global__ void hist_kernel(const int* __restrict__ head, int E) {
    int e = blockIdx.x * blockDim.x + threadIdx.x;
    if (e < E) atomicAdd(&g_hist[head[e]], 1);
}

// ---------------------------------------------------------------------------
// decoupled scan: per-block exclusive scan + block sums
// ---------------------------------------------------------------------------
__global__ void scan_part_kernel(int Nn) {
    __shared__ int swarp[32];
    int tid = threadIdx.x, lane = tid & 31, wid = tid >> 5;
    int i = blockIdx.x * 1024 + tid;
    int v = (i < Nn) ? g_hist[i] : 0;
    int incl = v;
    #pragma unroll
    for (int off = 1; off < 32; off <<= 1) {
        int t = __shfl_up_sync(0xffffffffu, incl, off);
        if (lane >= off) incl += t;
    }
    if (lane == 31) swarp[wid] = incl;
    __syncthreads();
    if (wid == 0) {
        int wv = swarp[lane];
        int winc = wv;
        #pragma unroll
        for (int off = 1; off < 32; off <<= 1) {
            int t = __shfl_up_sync(0xffffffffu, winc, off);
            if (lane >= off) winc += t;
        }
        swarp[lane] = winc - wv;
    }
    __syncthreads();
    int excl = swarp[wid] + incl - v;
    if (i < Nn) g_offs[i] = excl;
    if (tid == 1023) g_bsum[blockIdx.x] = excl + v;
}

// single block: exclusive scan of block sums in place (nb <= 1024)
__global__ void scan_bsum_kernel(int nb) {
    __shared__ int swarp[32];
    int tid = threadIdx.x, lane = tid & 31, wid = tid >> 5;
    int v = (tid < nb) ? g_bsum[tid] : 0;
    int incl = v;
    #pragma unroll
    for (int off = 1; off < 32; off <<= 1) {
        int t = __shfl_up_sync(0xffffffffu, incl, off);
        if (lane >= off) incl += t;
    }
    if (lane == 31) swarp[wid] = incl;
    __syncthreads();
    if (wid == 0) {
        int wv = swarp[lane];
        int winc = wv;
        #pragma unroll
        for (int off = 1; off < 32; off <<= 1) {
            int t = __shfl_up_sync(0xffffffffu, winc, off);
            if (lane >= off) winc += t;
        }
        swarp[lane] = winc - wv;
    }
    __syncthreads();
    if (tid < nb) g_bsum[tid] = swarp[wid] + incl - v;
}

__global__ void scan_add_kernel(int Nn, int E) {
    int i = blockIdx.x * blockDim.x + threadIdx.x;
    if (i < Nn) g_offs[i] += g_bsum[i >> 10];
    if (i == 0) g_offs[Nn] = E;
}

// ---------------------------------------------------------------------------
// scatter edges into head-sorted order
// ---------------------------------------------------------------------------
__global__ void sortscatter_kernel(const int* __restrict__ head,
                                   const int* __restrict__ tail,
                                   const int* __restrict__ bins, int E) {
    int e = blockIdx.x * blockDim.x + threadIdx.x;
    if (e >= E) return;
    int h = head[e];
    int p = g_offs[h] + atomicAdd(&g_cnt[h], 1);
    g_tail_s[p] = tail[e];
    g_bins_s[p] = bins[e];
}

// ---------------------------------------------------------------------------
// Fused per-node GEMM (tf32 tensor cores), cp.async double-buffered A,
// register-prefetched B, pre-rounded operands (no cvt in loop).
// Block 128x64, BK=32, 256 threads = 8 warps (4x2), warp tile 32x32.
// ---------------------------------------------------------------------------
#define BM 128
#define BN 64
#define BK 32
#define LDP 36   // row pitch in floats (BK + 4)

__global__ void gemm_tf32_kernel(const float* __restrict__ proj_b,
                                 const float* __restrict__ aggr_b,
                                 int Nn)
{
    __shared__ float As[2][BM * LDP];   // 36864 B
    __shared__ float Bs[BN * LDP];      //  9216 B

    const int m0    = blockIdx.x * BM;
    const int jbase = blockIdx.y * BN;

    const int tid  = threadIdx.x;
    const int lane = tid & 31;
    const int wid  = tid >> 5;
    const int wm   = wid >> 1;
    const int wn   = wid & 1;
    const int qrow = lane >> 2;
    const int qcol = lane & 3;

    const int arow = tid >> 3;          // 0..31 (+32 per t)
    const int ac4  = (tid & 7) << 2;

    float acc[2][4][4];
    #pragma unroll
    for (int i = 0; i < 2; i++)
        #pragma unroll
        for (int j = 0; j < 4; j++)
            #pragma unroll
            for (int k = 0; k < 4; k++) acc[i][j][k] = 0.f;

    uint32_t as_base = (uint32_t)__cvta_generic_to_shared(&As[0][0]);

    // prologue: cp.async stage 0, B regs for k0=0
    #pragma unroll
    for (int t = 0; t < 4; t++) {
        int row = arow + t * 32;
        int gm  = m0 + row;
        cp_async16(as_base + (row * LDP + ac4) * 4,
                   &g_embr[(size_t)gm * 256 + ac4], gm < Nn ? 16 : 0);
    }
    CP_COMMIT();
    float4 breg[2];
    #pragma unroll
    for (int t = 0; t < 2; t++) {
        int row = arow + t * 32;
        breg[t] = *(const float4*)&g_W[(size_t)(jbase + row) * 256 + ac4];
    }

    for (int it = 0; it < 8; it++) {
        const int st = it & 1;
        CP_WAIT0();
        __syncthreads();   // A stage ready; prior compute done (Bs, As[st^1] free)

        // store B regs to smem
        #pragma unroll
        for (int t = 0; t < 2; t++) {
            int row = arow + t * 32;
            *(float4*)&Bs[row * LDP + ac4] = breg[t];
        }

        if (it < 7) {
            int k0 = (it + 1) * BK;
            uint32_t dst = as_base + (st ^ 1) * (BM * LDP * 4);
            #pragma unroll
            for (int t = 0; t < 4; t++) {
                int row = arow + t * 32;
                int gm  = m0 + row;
                cp_async16(dst + (row * LDP + ac4) * 4,
                           &g_embr[(size_t)gm * 256 + k0 + ac4], gm < Nn ? 16 : 0);
            }
            CP_COMMIT();
            #pragma unroll
            for (int t = 0; t < 2; t++) {
                int row = arow + t * 32;
                breg[t] = *(const float4*)&g_W[(size_t)(jbase + row) * 256 + k0 + ac4];
            }
        }
        __syncthreads();   // Bs visible

        const float* Ax = &As[st][0];
        #pragma unroll
        for (int ks = 0; ks < BK / 8; ks++) {
            const int c = ks * 8 + qcol;
            uint32_t a[2][4];
            #pragma unroll
            for (int mf = 0; mf < 2; mf++) {
                int r = wm * 32 + mf * 16 + qrow;
                a[mf][0] = __float_as_uint(Ax[r * LDP + c]);
                a[mf][1] = __float_as_uint(Ax[(r + 8) * LDP + c]);
                a[mf][2] = __float_as_uint(Ax[r * LDP + c + 4]);
                a[mf][3] = __float_as_uint(Ax[(r + 8) * LDP + c + 4]);
            }
            uint32_t b[4][2];
            #pragma unroll
            for (int nf = 0; nf < 4; nf++) {
                int n = wn * 32 + nf * 8 + qrow;
                b[nf][0] = __float_as_uint(Bs[n * LDP + c]);
                b[nf][1] = __float_as_uint(Bs[n * LDP + c + 4]);
            }
            #pragma unroll
            for (int mf = 0; mf < 2; mf++)
                #pragma unroll
                for (int nf = 0; nf < 4; nf++) {
                    asm volatile(
                        "mma.sync.aligned.m16n8k8.row.col.f32.tf32.tf32.f32 "
                        "{%0,%1,%2,%3}, {%4,%5,%6,%7}, {%8,%9}, {%0,%1,%2,%3};"
                        : "+f"(acc[mf][nf][0]), "+f"(acc[mf][nf][1]),
                          "+f"(acc[mf][nf][2]), "+f"(acc[mf][nf][3])
                        : "r"(a[mf][0]), "r"(a[mf][1]), "r"(a[mf][2]), "r"(a[mf][3]),
                          "r"(b[nf][0]), "r"(b[nf][1]));
                }
        }
        __syncthreads();   // compute done before next iter overwrites Bs / As[st^1]
    }

    // epilogue -> fp16 g_Ph
    #pragma unroll
    for (int mf = 0; mf < 2; mf++) {
        #pragma unroll
        for (int nf = 0; nf < 4; nf++) {
            int gc = jbase + wn * 32 + nf * 8 + 2 * qcol;
            float b0 = 0.f, b1 = 0.f;
            if (gc < 256)       { b0 = proj_b[gc];       b1 = proj_b[gc + 1]; }
            else if (gc >= 512) { b0 = aggr_b[gc - 512]; b1 = aggr_b[gc - 511]; }
            int gr0 = m0 + wm * 32 + mf * 16 + qrow;
            int gr1 = gr0 + 8;
            if (gr0 < Nn)
                *(__half2*)&g_Ph[(size_t)gr0 * 768 + gc] =
                    __floats2half2_rn(acc[mf][nf][0] + b0, acc[mf][nf][1] + b1);
            if (gr1 < Nn)
                *(__half2*)&g_Ph[(size_t)gr1 * 768 + gc] =
                    __floats2half2_rn(acc[mf][nf][2] + b0, acc[mf][nf][3] + b1);
        }
    }
}

// ---------------------------------------------------------------------------
// Per-node fused attention + aggregation: one warp per head node.
// Online softmax, no atomics, plain stores.
// ---------------------------------------------------------------------------
__global__ void node_kernel(const float* __restrict__ attn_vec, // 256
                            const float* __restrict__ attn_bin, // 10*8
                            float* __restrict__ out, int Nn)
{
    __shared__ float sav[256];
    __shared__ float sbin[80];
    for (int i = threadIdx.x; i < 256; i += blockDim.x) sav[i] = attn_vec[i];
    for (int i = threadIdx.x; i < 80;  i += blockDim.x) sbin[i] = attn_bin[i];
    __syncthreads();

    int n    = (blockIdx.x * blockDim.x + threadIdx.x) >> 5;
    int lane = threadIdx.x & 31;
    if (n >= Nn) return;

    int beg = g_offs[n];
    int cnt = g_offs[n + 1] - beg;
    const int d0 = lane * 8;
    const int hsel = lane >> 2;

    uint4 xu = *(const uint4*)(g_Ph + (size_t)n * 768 + d0);

    float m = __int_as_float(0xff800000);
    float ssum = 0.f;
    float accv[8];
    #pragma unroll
    for (int q = 0; q < 8; q++) accv[q] = 0.f;

    uint4 yu_n = make_uint4(0,0,0,0), au_n = make_uint4(0,0,0,0);
    int bn_n = 0;
    if (cnt > 0) {
        int tl = g_tail_s[beg];
        bn_n = g_bins_s[beg];
        const __half* pr = g_Ph + (size_t)tl * 768;
        yu_n = *(const uint4*)(pr + 256 + d0);
        au_n = *(const uint4*)(pr + 512 + d0);
    }

    for (int i = 0; i < cnt; i++) {
        uint4 yu = yu_n, au = au_n;
        int be = bn_n;
        if (i + 1 < cnt) {
            int tl = g_tail_s[beg + i + 1];
            bn_n = g_bins_s[beg + i + 1];
            const __half* pr = g_Ph + (size_t)tl * 768;
            yu_n = *(const uint4*)(pr + 256 + d0);
            au_n = *(const uint4*)(pr + 512 + d0);
        }

        const uint32_t* xp = &xu.x;
        const uint32_t* yp = &yu.x;
        float s = 0.f;
        #pragma unroll
        for (int q = 0; q < 4; q++) {
            float2 fx = __half22float2(*(const __half2*)&xp[q]);
            float2 fy = __half22float2(*(const __half2*)&yp[q]);
            int d = d0 + q * 2;
            float v;
            v = fx.x + fy.x; v = v >= 0.f ? v : 0.2f * v; s += v * sav[d + 0];
            v = fx.y + fy.y; v = v >= 0.f ? v : 0.2f * v; s += v * sav[d + 1];
        }
        s += __shfl_xor_sync(0xffffffffu, s, 1);
        s += __shfl_xor_sync(0xffffffffu, s, 2);

        float raw = s + sbin[be * 8 + hsel];

        float mn    = fmaxf(m, raw);
        float scale = __expf(m - mn);
        float ev    = __expf(raw - mn);
        ssum = ssum * scale + ev;
        m = mn;

        const uint32_t* ap = &au.x;
        #pragma unroll
        for (int q = 0; q < 4; q++) {
            float2 fa = __half22float2(*(const __half2*)&ap[q]);
            accv[q * 2 + 0] = accv[q * 2 + 0] * scale + ev * fa.x;
            accv[q * 2 + 1] = accv[q * 2 + 1] * scale + ev * fa.y;
        }
    }

    float inv = 1.f / (ssum + 1e-16f);
    float4 o0 = make_float4(accv[0] * inv, accv[1] * inv, accv[2] * inv, accv[3] * inv);
    float4 o1 = make_float4(accv[4] * inv, accv[5] * inv, accv[6] * inv, accv[7] * inv);
    float* op = out + (size_t)n * 256 + d0;
    *(float4*)op       = o0;
    *(float4*)(op + 4) = o1;
}

// ---------------------------------------------------------------------------
extern "C" void kernel_launch(void* const* d_in, const int* in_sizes, int n_in,
                              void* d_out, int out_size)
{
    const float* emb      = (const float*)d_in[0];
    const int*   head     = (const int*)  d_in[1];
    const int*   tail     = (const int*)  d_in[2];
    const int*   bins     = (const int*)  d_in[3];
    const float* attn_w   = (const float*)d_in[4];
    const float* proj_b   = (const float*)d_in[5];
    const float* attn_bin = (const float*)d_in[6];
    const float* attn_vec = (const float*)d_in[7];
    const float* aggr_w   = (const float*)d_in[8];
    const float* aggr_b   = (const float*)d_in[9];
    float* out = (float*)d_out;

    int Nn = in_sizes[0] / 256;
    int E  = in_sizes[1];

    // index pipeline (independent of GEMM)
    zero_kernel<<<(Nn + 255) / 256, 256>>>(Nn);
    hist_kernel<<<(E + 255) / 256, 256>>>(head, E);
    int nb = (Nn + 1023) / 1024;
    scan_part_kernel<<<nb, 1024>>>(Nn);
    scan_bsum_kernel<<<1, 1024>>>(nb);
    scan_add_kernel<<<(Nn + 255) / 256, 256>>>(Nn, E);
    sortscatter_kernel<<<(E + 255) / 256, 256>>>(head, tail, bins, E);

    // GEMM pipeline
    int n4 = Nn * 64;
    round_emb_kernel<<<(n4 + 255) / 256, 256>>>(emb, n4);
    round_w_kernel<<<(768 * 64 + 255) / 256, 256>>>(attn_w, aggr_w);
    dim3 ggrid((Nn + BM - 1) / BM, 768 / BN);
    gemm_tf32_kernel<<<ggrid, 256>>>(proj_b, aggr_b, Nn);

    // fused per-node attention + aggregation
    node_kernel<<<(Nn * 32 + 255) / 256, 256>>>(attn_vec, attn_bin, out, Nn);
}

// round 6
// speedup vs baseline: 2.8885x; 1.0352x over previous
#include <cuda_runtime.h>
#include <cuda_fp16.h>
#include <cstdint>

#define NMAX 50000
#define EMAX 500000

// Scratch (static device globals -- no allocation allowed)
__device__ __half g_Ph[(size_t)NMAX * 768]; // 0-255: W1*x+b, 256-511: W2*x, 512-767: Wagg*x+b_agg (fp16)
__device__ int    g_hist[NMAX];
__device__ int    g_cnt[NMAX];
__device__ int    g_offs[NMAX + 1];
__device__ int    g_bsum[1024];
__device__ int    g_es[EMAX];               // packed: tail | bin<<20 (head-sorted)

__device__ __forceinline__ float to_tf32(float x) {
    float r;
    asm("cvt.rna.tf32.f32 %0, %1;" : "=f"(r) : "f"(x));
    return r;
}

__device__ __forceinline__ void cp_async16(uint32_t saddr, const void* gptr, int src_size) {
    asm volatile("cp.async.cg.shared.global [%0], [%1], 16, %2;"
                 :: "r"(saddr), "l"(gptr), "r"(src_size));
}
#define CP_COMMIT() asm volatile("cp.async.commit_group;")
#define CP_WAIT0()  asm volatile("cp.async.wait_group 0;")

// ---------------------------------------------------------------------------
__global__ void zero_kernel(int Nn) {
    int i = blockIdx.x * blockDim.x + threadIdx.x;
    if (i < Nn) { g_hist[i] = 0; g_cnt[i] = 0; }
}

__global__ void hist_kernel(const int* __restrict__ head, int E) {
    int e = blockIdx.x * blockDim.x + threadIdx.x;
    if (e < E) atomicAdd(&g_hist[head[e]], 1);
}

// ---------------------------------------------------------------------------
// decoupled scan
// ---------------------------------------------------------------------------
__global__ void scan_part_kernel(int Nn) {
    __shared__ int swarp[32];
    int tid = threadIdx.x, lane = tid & 31, wid = tid >> 5;
    int i = blockIdx.x * 1024 + tid;
    int v = (i < Nn) ? g_hist[i] : 0;
    int incl = v;
    #pragma unroll
    for (int off = 1; off < 32; off <<= 1) {
        int t = __shfl_up_sync(0xffffffffu, incl, off);
        if (lane >= off) incl += t;
    }
    if (lane == 31) swarp[wid] = incl;
    __syncthreads();
    if (wid == 0) {
        int wv = swarp[lane];
        int winc = wv;
        #pragma unroll
        for (int off = 1; off < 32; off <<= 1) {
            int t = __shfl_up_sync(0xffffffffu, winc, off);
            if (lane >= off) winc += t;
        }
        swarp[lane] = winc - wv;
    }
    __syncthreads();
    int excl = swarp[wid] + incl - v;
    if (i < Nn) g_offs[i] = excl;
    if (tid == 1023) g_bsum[blockIdx.x] = excl + v;
}

__global__ void scan_bsum_kernel(int nb) {
    __shared__ int swarp[32];
    int tid = threadIdx.x, lane = tid & 31, wid = tid >> 5;
    int v = (tid < nb) ? g_bsum[tid] : 0;
    int incl = v;
    #pragma unroll
    for (int off = 1; off < 32; off <<= 1) {
        int t = __shfl_up_sync(0xffffffffu, incl, off);
        if (lane >= off) incl += t;
    }
    if (lane == 31) swarp[wid] = incl;
    __syncthreads();
    if (wid == 0) {
        int wv = swarp[lane];
        int winc = wv;
        #pragma unroll
        for (int off = 1; off < 32; off <<= 1) {
            int t = __shfl_up_sync(0xffffffffu, winc, off);
            if (lane >= off) winc += t;
        }
        swarp[lane] = winc - wv;
    }
    __syncthreads();
    if (tid < nb) g_bsum[tid] = swarp[wid] + incl - v;
}

__global__ void scan_add_kernel(int Nn, int E) {
    int i = blockIdx.x * blockDim.x + threadIdx.x;
    if (i < Nn) g_offs[i] += g_bsum[i >> 10];
    if (i == 0) g_offs[Nn] = E;
}

// ---------------------------------------------------------------------------
// scatter edges into head-sorted order; pack (tail, bin) into one int
// ---------------------------------------------------------------------------
__global__ void sortscatter_kernel(const int* __restrict__ head,
                                   const int* __restrict__ tail,
                                   const int* __restrict__ bins, int E) {
    int e = blockIdx.x * blockDim.x + threadIdx.x;
    if (e >= E) return;
    int h = head[e];
    int p = g_offs[h] + atomicAdd(&g_cnt[h], 1);
    g_es[p] = tail[e] | (bins[e] << 20);
}

// ---------------------------------------------------------------------------
// Fused per-node GEMM (tf32 tensor cores), cp.async double-buffered A.
// Block 128x128, BK=16, 256 threads = 8 warps (4x2), warp tile 32x64.
// In-register tf32 rounding (rna): B at smem-store, A at operand-load.
// ---------------------------------------------------------------------------
#define BM 128
#define BN 128
#define BK 16
#define LDP 20   // row pitch in floats (BK + 4)

__global__ void __launch_bounds__(256)
gemm_tf32_kernel(const float* __restrict__ emb,
                 const float* __restrict__ attn_w,   // (256, 512) row-major
                 const float* __restrict__ aggr_w,   // (256, 256) row-major
                 const float* __restrict__ proj_b,   // (256)
                 const float* __restrict__ aggr_b,   // (256)
                 int Nn)
{
    __shared__ float As[2][BM * LDP];   // 20480 B
    __shared__ float Bs[BN * LDP];      // 10240 B

    const int m0    = blockIdx.x * BM;
    const int jbase = blockIdx.y * BN;  // 0,128,256,384,512,640 -> single region each

    const float* Bptr;
    int ldb;
    if (jbase < 256)      { Bptr = attn_w + (size_t)jbase * 512;               ldb = 512; }
    else if (jbase < 512) { Bptr = attn_w + (size_t)(jbase - 256) * 512 + 256; ldb = 512; }
    else                  { Bptr = aggr_w + (size_t)(jbase - 512) * 256;       ldb = 256; }

    const int tid  = threadIdx.x;
    const int lane = tid & 31;
    const int wid  = tid >> 5;
    const int wm   = wid >> 1;          // 0..3 -> rows [wm*32, +32)
    const int wn   = wid & 1;           // 0..1 -> cols [wn*64, +64)
    const int qrow = lane >> 2;
    const int qcol = lane & 3;

    const int lrow = tid >> 2;          // 0..63 (+64 per t)
    const int lc4  = (tid & 3) << 2;    // 0,4,8,12

    float acc[2][8][4];
    #pragma unroll
    for (int i = 0; i < 2; i++)
        #pragma unroll
        for (int j = 0; j < 8; j++)
            #pragma unroll
            for (int k = 0; k < 4; k++) acc[i][j][k] = 0.f;

    uint32_t as_base = (uint32_t)__cvta_generic_to_shared(&As[0][0]);

    // prologue: cp.async A stage 0; B regs for k0=0
    #pragma unroll
    for (int t = 0; t < 2; t++) {
        int row = lrow + t * 64;
        int gm  = m0 + row;
        cp_async16(as_base + (row * LDP + lc4) * 4,
                   &emb[(size_t)gm * 256 + lc4], gm < Nn ? 16 : 0);
    }
    CP_COMMIT();
    float4 breg[2];
    #pragma unroll
    for (int t = 0; t < 2; t++) {
        int row = lrow + t * 64;
        breg[t] = *(const float4*)&Bptr[(size_t)row * ldb + lc4];
    }

    for (int it = 0; it < 16; it++) {
        const int st = it & 1;
        CP_WAIT0();
        __syncthreads();   // A stage ready; prior compute done

        // store B regs (rounded) to smem
        #pragma unroll
        for (int t = 0; t < 2; t++) {
            int row = lrow + t * 64;
            Bs[row * LDP + lc4 + 0] = to_tf32(breg[t].x);
            Bs[row * LDP + lc4 + 1] = to_tf32(breg[t].y);
            Bs[row * LDP + lc4 + 2] = to_tf32(breg[t].z);
            Bs[row * LDP + lc4 + 3] = to_tf32(breg[t].w);
        }

        if (it < 15) {
            int k0 = (it + 1) * BK;
            uint32_t dst = as_base + (st ^ 1) * (BM * LDP * 4);
            #pragma unroll
            for (int t = 0; t < 2; t++) {
                int row = lrow + t * 64;
                int gm  = m0 + row;
                cp_async16(dst + (row * LDP + lc4) * 4,
                           &emb[(size_t)gm * 256 + k0 + lc4], gm < Nn ? 16 : 0);
            }
            CP_COMMIT();
            #pragma unroll
            for (int t = 0; t < 2; t++) {
                int row = lrow + t * 64;
                breg[t] = *(const float4*)&Bptr[(size_t)row * ldb + k0 + lc4];
            }
        }
        __syncthreads();   // Bs visible

        const float* Ax = &As[st][0];
        #pragma unroll
        for (int ks = 0; ks < BK / 8; ks++) {
            const int c = ks * 8 + qcol;
            uint32_t a[2][4];
            #pragma unroll
            for (int mf = 0; mf < 2; mf++) {
                int r = wm * 32 + mf * 16 + qrow;
                a[mf][0] = __float_as_uint(to_tf32(Ax[r * LDP + c]));
                a[mf][1] = __float_as_uint(to_tf32(Ax[(r + 8) * LDP + c]));
                a[mf][2] = __float_as_uint(to_tf32(Ax[r * LDP + c + 4]));
                a[mf][3] = __float_as_uint(to_tf32(Ax[(r + 8) * LDP + c + 4]));
            }
            uint32_t b[8][2];
            #pragma unroll
            for (int nf = 0; nf < 8; nf++) {
                int n = wn * 64 + nf * 8 + qrow;
                b[nf][0] = __float_as_uint(Bs[n * LDP + c]);
                b[nf][1] = __float_as_uint(Bs[n * LDP + c + 4]);
            }
            #pragma unroll
            for (int mf = 0; mf < 2; mf++)
                #pragma unroll
                for (int nf = 0; nf < 8; nf++) {
                    asm volatile(
                        "mma.sync.aligned.m16n8k8.row.col.f32.tf32.tf32.f32 "
                        "{%0,%1,%2,%3}, {%4,%5,%6,%7}, {%8,%9}, {%0,%1,%2,%3};"
                        : "+f"(acc[mf][nf][0]), "+f"(acc[mf][nf][1]),
                          "+f"(acc[mf][nf][2]), "+f"(acc[mf][nf][3])
                        : "r"(a[mf][0]), "r"(a[mf][1]), "r"(a[mf][2]), "r"(a[mf][3]),
                          "r"(b[nf][0]), "r"(b[nf][1]));
                }
        }
        __syncthreads();   // compute done before next iter overwrites smem
    }

    // epilogue -> fp16 g_Ph
    #pragma unroll
    for (int mf = 0; mf < 2; mf++) {
        #pragma unroll
        for (int nf = 0; nf < 8; nf++) {
            int gc = jbase + wn * 64 + nf * 8 + 2 * qcol;
            float b0 = 0.f, b1 = 0.f;
            if (gc < 256)       { b0 = proj_b[gc];       b1 = proj_b[gc + 1]; }
            else if (gc >= 512) { b0 = aggr_b[gc - 512]; b1 = aggr_b[gc - 511]; }
            int gr0 = m0 + wm * 32 + mf * 16 + qrow;
            int gr1 = gr0 + 8;
            if (gr0 < Nn)
                *(__half2*)&g_Ph[(size_t)gr0 * 768 + gc] =
                    __floats2half2_rn(acc[mf][nf][0] + b0, acc[mf][nf][1] + b1);
            if (gr1 < Nn)
                *(__half2*)&g_Ph[(size_t)gr1 * 768 + gc] =
                    __floats2half2_rn(acc[mf][nf][2] + b0, acc[mf][nf][3] + b1);
        }
    }
}

// ---------------------------------------------------------------------------
// Per-node fused attention + aggregation: one warp per head node.
// Online softmax, no atomics, plain stores. Packed edge records.
// ---------------------------------------------------------------------------
__global__ void node_kernel(const float* __restrict__ attn_vec, // 256
                            const float* __restrict__ attn_bin, // 10*8
                            float* __restrict__ out, int Nn)
{
    __shared__ float sav[256];
    __shared__ float sbin[80];
    for (int i = threadIdx.x; i < 256; i += blockDim.x) sav[i] = attn_vec[i];
    for (int i = threadIdx.x; i < 80;  i += blockDim.x) sbin[i] = attn_bin[i];
    __syncthreads();

    int n    = (blockIdx.x * blockDim.x + threadIdx.x) >> 5;
    int lane = threadIdx.x & 31;
    if (n >= Nn) return;

    int beg = g_offs[n];
    int cnt = g_offs[n + 1] - beg;
    const int d0 = lane * 8;
    const int hsel = lane >> 2;

    uint4 xu = *(const uint4*)(g_Ph + (size_t)n * 768 + d0);

    float m = __int_as_float(0xff800000);
    float ssum = 0.f;
    float accv[8];
    #pragma unroll
    for (int q = 0; q < 8; q++) accv[q] = 0.f;

    uint4 yu_n = make_uint4(0,0,0,0), au_n = make_uint4(0,0,0,0);
    int pk_n = 0;
    if (cnt > 0) {
        pk_n = g_es[beg];
        const __half* pr = g_Ph + (size_t)(pk_n & 0xFFFFF) * 768;
        yu_n = *(const uint4*)(pr + 256 + d0);
        au_n = *(const uint4*)(pr + 512 + d0);
    }

    for (int i = 0; i < cnt; i++) {
        uint4 yu = yu_n, au = au_n;
        int be = pk_n >> 20;
        if (i + 1 < cnt) {
            pk_n = g_es[beg + i + 1];
            const __half* pr = g_Ph + (size_t)(pk_n & 0xFFFFF) * 768;
            yu_n = *(const uint4*)(pr + 256 + d0);
            au_n = *(const uint4*)(pr + 512 + d0);
        }

        const uint32_t* xp = &xu.x;
        const uint32_t* yp = &yu.x;
        float s = 0.f;
        #pragma unroll
        for (int q = 0; q < 4; q++) {
            float2 fx = __half22float2(*(const __half2*)&xp[q]);
            float2 fy = __half22float2(*(const __half2*)&yp[q]);
            int d = d0 + q * 2;
            float v;
            v = fx.x + fy.x; v = v >= 0.f ? v : 0.2f * v; s += v * sav[d + 0];
            v = fx.y + fy.y; v = v >= 0.f ? v : 0.2f * v; s += v * sav[d + 1];
        }
        s += __shfl_xor_sync(0xffffffffu, s, 1);
        s += __shfl_xor_sync(0xffffffffu, s, 2);

        float raw = s + sbin[be * 8 + hsel];

        float mn    = fmaxf(m, raw);
        float scale = __expf(m - mn);
        float ev    = __expf(raw - mn);
        ssum = ssum * scale + ev;
        m = mn;

        const uint32_t* ap = &au.x;
        #pragma unroll
        for (int q = 0; q < 4; q++) {
            float2 fa = __half22float2(*(const __half2*)&ap[q]);
            accv[q * 2 + 0] = accv[q * 2 + 0] * scale + ev * fa.x;
            accv[q * 2 + 1] = accv[q * 2 + 1] * scale + ev * fa.y;
        }
    }

    float inv = 1.f / (ssum + 1e-16f);
    float4 o0 = make_float4(accv[0] * inv, accv[1] * inv, accv[2] * inv, accv[3] * inv);
    float4 o1 = make_float4(accv[4] * inv, accv[5] * inv, accv[6] * inv, accv[7] * inv);
    float* op = out + (size_t)n * 256 + d0;
    *(float4*)op       = o0;
    *(float4*)(op + 4) = o1;
}

// ---------------------------------------------------------------------------
extern "C" void kernel_launch(void* const* d_in, const int* in_sizes, int n_in,
                              void* d_out, int out_size)
{
    const float* emb      = (const float*)d_in[0];
    const int*   head     = (const int*)  d_in[1];
    const int*   tail     = (const int*)  d_in[2];
    const int*   bins     = (const int*)  d_in[3];
    const float* attn_w   = (const float*)d_in[4];
    const float* proj_b   = (const float*)d_in[5];
    const float* attn_bin = (const float*)d_in[6];
    const float* attn_vec = (const float*)d_in[7];
    const float* aggr_w   = (const float*)d_in[8];
    const float* aggr_b   = (const float*)d_in[9];
    float* out = (float*)d_out;

    int Nn = in_sizes[0] / 256;
    int E  = in_sizes[1];
    int nb = (Nn + 1023) / 1024;

    // launch order chosen so the GEMM sits at index 3 (ncu profiles launch #3)
    zero_kernel<<<(Nn + 255) / 256, 256>>>(Nn);                          // 0
    hist_kernel<<<(E + 255) / 256, 256>>>(head, E);                      // 1
    scan_part_kernel<<<nb, 1024>>>(Nn);                                  // 2
    dim3 ggrid((Nn + BM - 1) / BM, 768 / BN);
    gemm_tf32_kernel<<<ggrid, 256>>>(emb, attn_w, aggr_w, proj_b, aggr_b, Nn); // 3 <- profiled
    scan_bsum_kernel<<<1, 1024>>>(nb);                                   // 4
    scan_add_kernel<<<(Nn + 255) / 256, 256>>>(Nn, E);                   // 5
    sortscatter_kernel<<<(E + 255) / 256, 256>>>(head, tail, bins, E);   // 6
    node_kernel<<<(Nn * 32 + 255) / 256, 256>>>(attn_vec, attn_bin, out, Nn); // 7
}

// round 7
// speedup vs baseline: 3.0230x; 1.0465x over previous
#include <cuda_runtime.h>
#include <cuda_fp16.h>
#include <cstdint>

#define NMAX 50000
#define EMAX 500000

// Scratch (static device globals -- no allocation allowed)
__device__ __half g_Ph[(size_t)NMAX * 768]; // 0-255: W1*x+b, 256-511: W2*x, 512-767: Wagg*x+b_agg (fp16)
__device__ int    g_hist[NMAX];
__device__ int    g_cnt[NMAX];
__device__ int    g_offs[NMAX + 1];
__device__ int    g_bsum[1024];
__device__ int    g_es[EMAX];               // packed: tail | bin<<20 (head-sorted)

// ---------------------------------------------------------------------------
__global__ void zero_kernel(int Nn) {
    int i = blockIdx.x * blockDim.x + threadIdx.x;
    if (i < Nn) { g_hist[i] = 0; g_cnt[i] = 0; }
}

__global__ void hist_kernel(const int* __restrict__ head, int E) {
    int e = blockIdx.x * blockDim.x + threadIdx.x;
    if (e < E) atomicAdd(&g_hist[head[e]], 1);
}

// ---------------------------------------------------------------------------
// decoupled scan
// ---------------------------------------------------------------------------
__global__ void scan_part_kernel(int Nn) {
    __shared__ int swarp[32];
    int tid = threadIdx.x, lane = tid & 31, wid = tid >> 5;
    int i = blockIdx.x * 1024 + tid;
    int v = (i < Nn) ? g_hist[i] : 0;
    int incl = v;
    #pragma unroll
    for (int off = 1; off < 32; off <<= 1) {
        int t = __shfl_up_sync(0xffffffffu, incl, off);
        if (lane >= off) incl += t;
    }
    if (lane == 31) swarp[wid] = incl;
    __syncthreads();
    if (wid == 0) {
        int wv = swarp[lane];
        int winc = wv;
        #pragma unroll
        for (int off = 1; off < 32; off <<= 1) {
            int t = __shfl_up_sync(0xffffffffu, winc, off);
            if (lane >= off) winc += t;
        }
        swarp[lane] = winc - wv;
    }
    __syncthreads();
    int excl = swarp[wid] + incl - v;
    if (i < Nn) g_offs[i] = excl;
    if (tid == 1023) g_bsum[blockIdx.x] = excl + v;
}

__global__ void scan_bsum_kernel(int nb) {
    __shared__ int swarp[32];
    int tid = threadIdx.x, lane = tid & 31, wid = tid >> 5;
    int v = (tid < nb) ? g_bsum[tid] : 0;
    int incl = v;
    #pragma unroll
    for (int off = 1; off < 32; off <<= 1) {
        int t = __shfl_up_sync(0xffffffffu, incl, off);
        if (lane >= off) incl += t;
    }
    if (lane == 31) swarp[wid] = incl;
    __syncthreads();
    if (wid == 0) {
        int wv = swarp[lane];
        int winc = wv;
        #pragma unroll
        for (int off = 1; off < 32; off <<= 1) {
            int t = __shfl_up_sync(0xffffffffu, winc, off);
            if (lane >= off) winc += t;
        }
        swarp[lane] = winc - wv;
    }
    __syncthreads();
    if (tid < nb) g_bsum[tid] = swarp[wid] + incl - v;
}

__global__ void scan_add_kernel(int Nn, int E) {
    int i = blockIdx.x * blockDim.x + threadIdx.x;
    if (i < Nn) g_offs[i] += g_bsum[i >> 10];
    if (i == 0) g_offs[Nn] = E;
}

// ---------------------------------------------------------------------------
// scatter edges into head-sorted order; pack (tail, bin) into one int
// ---------------------------------------------------------------------------
__global__ void sortscatter_kernel(const int* __restrict__ head,
                                   const int* __restrict__ tail,
                                   const int* __restrict__ bins, int E) {
    int e = blockIdx.x * blockDim.x + threadIdx.x;
    if (e >= E) return;
    int h = head[e];
    int p = g_offs[h] + atomicAdd(&g_cnt[h], 1);
    g_es[p] = tail[e] | (bins[e] << 20);
}

// ---------------------------------------------------------------------------
// Fused per-node GEMM, fp16 tensor cores (mma.m16n8k16, fp32 accum).
// Block 128x128, BK=32, 256 threads = 8 warps (4x2), warp tile 32x64.
// Operands converted fp32->fp16 at smem-store time; reg-prefetch pipeline.
// ---------------------------------------------------------------------------
#define BM 128
#define BN 128
#define BK 32
#define HP 40    // smem row pitch in halfs (32 + 8); 80 B/row -> conflict-free frags

__global__ void __launch_bounds__(256)
gemm_f16_kernel(const float* __restrict__ emb,
                const float* __restrict__ attn_w,   // (256, 512) row-major
                const float* __restrict__ aggr_w,   // (256, 256) row-major
                const float* __restrict__ proj_b,   // (256)
                const float* __restrict__ aggr_b,   // (256)
                int Nn)
{
    __shared__ __half As[BM * HP];   // 10240 B
    __shared__ __half Bs[BN * HP];   // 10240 B

    const int m0    = blockIdx.x * BM;
    const int jbase = blockIdx.y * BN;  // 0,128,...,640 -> single weight region each

    const float* Bptr;
    int ldb;
    if (jbase < 256)      { Bptr = attn_w + (size_t)jbase * 512;               ldb = 512; }
    else if (jbase < 512) { Bptr = attn_w + (size_t)(jbase - 256) * 512 + 256; ldb = 512; }
    else                  { Bptr = aggr_w + (size_t)(jbase - 512) * 256;       ldb = 256; }

    const int tid  = threadIdx.x;
    const int lane = tid & 31;
    const int wid  = tid >> 5;
    const int wm   = wid >> 1;          // rows [wm*32, +32)
    const int wn   = wid & 1;           // cols [wn*64, +64)
    const int qrow = lane >> 2;         // groupID 0..7
    const int qcol = lane & 3;          // threadID-in-group 0..3

    // global-load mapping: each thread owns 16 consecutive k-floats of one row
    const int grow = tid >> 1;          // 0..127
    const int goff = (tid & 1) << 4;    // 0 or 16

    float acc[2][8][4];
    #pragma unroll
    for (int i = 0; i < 2; i++)
        #pragma unroll
        for (int j = 0; j < 8; j++)
            #pragma unroll
            for (int k = 0; k < 4; k++) acc[i][j][k] = 0.f;

    const int gm = m0 + grow;
    const float* arow_p = emb + (size_t)gm * 256 + goff;
    const float* brow_p = Bptr + (size_t)grow * ldb + goff;

    float4 ar[4], br[4];
    #pragma unroll
    for (int t = 0; t < 4; t++) {
        ar[t] = (gm < Nn) ? *(const float4*)(arow_p + t * 4) : make_float4(0.f,0.f,0.f,0.f);
        br[t] = *(const float4*)(brow_p + t * 4);
    }

    for (int it = 0; it < 8; it++) {
        __syncthreads();   // previous compute done

        // convert + store to smem (fp16), 16 halfs per thread per tile
        {
            __half2* ad = (__half2*)&As[grow * HP + goff];
            __half2* bd = (__half2*)&Bs[grow * HP + goff];
            #pragma unroll
            for (int t = 0; t < 4; t++) {
                ad[t * 2 + 0] = __floats2half2_rn(ar[t].x, ar[t].y);
                ad[t * 2 + 1] = __floats2half2_rn(ar[t].z, ar[t].w);
                bd[t * 2 + 0] = __floats2half2_rn(br[t].x, br[t].y);
                bd[t * 2 + 1] = __floats2half2_rn(br[t].z, br[t].w);
            }
        }

        if (it < 7) {
            int k0 = (it + 1) * BK;
            #pragma unroll
            for (int t = 0; t < 4; t++) {
                ar[t] = (gm < Nn) ? *(const float4*)(arow_p + k0 + t * 4)
                                  : make_float4(0.f,0.f,0.f,0.f);
                br[t] = *(const float4*)(brow_p + k0 + t * 4);
            }
        }
        __syncthreads();   // tiles visible

        #pragma unroll
        for (int ks = 0; ks < 2; ks++) {       // two k16 steps
            const int kb = ks * 16 + 2 * qcol; // half col of first pair
            uint32_t a[2][4];
            #pragma unroll
            for (int mf = 0; mf < 2; mf++) {
                int r = wm * 32 + mf * 16 + qrow;
                a[mf][0] = *(const uint32_t*)&As[r * HP + kb];
                a[mf][1] = *(const uint32_t*)&As[(r + 8) * HP + kb];
                a[mf][2] = *(const uint32_t*)&As[r * HP + kb + 8];
                a[mf][3] = *(const uint32_t*)&As[(r + 8) * HP + kb + 8];
            }
            uint32_t b[8][2];
            #pragma unroll
            for (int nf = 0; nf < 8; nf++) {
                int n = wn * 64 + nf * 8 + qrow;
                b[nf][0] = *(const uint32_t*)&Bs[n * HP + kb];
                b[nf][1] = *(const uint32_t*)&Bs[n * HP + kb + 8];
            }
            #pragma unroll
            for (int mf = 0; mf < 2; mf++)
                #pragma unroll
                for (int nf = 0; nf < 8; nf++) {
                    asm volatile(
                        "mma.sync.aligned.m16n8k16.row.col.f32.f16.f16.f32 "
                        "{%0,%1,%2,%3}, {%4,%5,%6,%7}, {%8,%9}, {%0,%1,%2,%3};"
                        : "+f"(acc[mf][nf][0]), "+f"(acc[mf][nf][1]),
                          "+f"(acc[mf][nf][2]), "+f"(acc[mf][nf][3])
                        : "r"(a[mf][0]), "r"(a[mf][1]), "r"(a[mf][2]), "r"(a[mf][3]),
                          "r"(b[nf][0]), "r"(b[nf][1]));
                }
        }
    }

    // epilogue -> fp16 g_Ph (same C-fragment layout as m16n8k8)
    #pragma unroll
    for (int mf = 0; mf < 2; mf++) {
        #pragma unroll
        for (int nf = 0; nf < 8; nf++) {
            int gc = jbase + wn * 64 + nf * 8 + 2 * qcol;
            float b0 = 0.f, b1 = 0.f;
            if (gc < 256)       { b0 = proj_b[gc];       b1 = proj_b[gc + 1]; }
            else if (gc >= 512) { b0 = aggr_b[gc - 512]; b1 = aggr_b[gc - 511]; }
            int gr0 = m0 + wm * 32 + mf * 16 + qrow;
            int gr1 = gr0 + 8;
            if (gr0 < Nn)
                *(__half2*)&g_Ph[(size_t)gr0 * 768 + gc] =
                    __floats2half2_rn(acc[mf][nf][0] + b0, acc[mf][nf][1] + b1);
            if (gr1 < Nn)
                *(__half2*)&g_Ph[(size_t)gr1 * 768 + gc] =
                    __floats2half2_rn(acc[mf][nf][2] + b0, acc[mf][nf][3] + b1);
        }
    }
}

// ---------------------------------------------------------------------------
// Per-node fused attention + aggregation: one warp per head node.
// Online softmax, no atomics, plain stores. Packed edge records.
// ---------------------------------------------------------------------------
__global__ void node_kernel(const float* __restrict__ attn_vec, // 256
                            const float* __restrict__ attn_bin, // 10*8
                            float* __restrict__ out, int Nn)
{
    __shared__ float sav[256];
    __shared__ float sbin[80];
    for (int i = threadIdx.x; i < 256; i += blockDim.x) sav[i] = attn_vec[i];
    for (int i = threadIdx.x; i < 80;  i += blockDim.x) sbin[i] = attn_bin[i];
    __syncthreads();

    int n    = (blockIdx.x * blockDim.x + threadIdx.x) >> 5;
    int lane = threadIdx.x & 31;
    if (n >= Nn) return;

    int beg = g_offs[n];
    int cnt = g_offs[n + 1] - beg;
    const int d0 = lane * 8;
    const int hsel = lane >> 2;

    uint4 xu = *(const uint4*)(g_Ph + (size_t)n * 768 + d0);

    float m = __int_as_float(0xff800000);
    float ssum = 0.f;
    float accv[8];
    #pragma unroll
    for (int q = 0; q < 8; q++) accv[q] = 0.f;

    uint4 yu_n = make_uint4(0,0,0,0), au_n = make_uint4(0,0,0,0);
    int pk_n = 0;
    if (cnt > 0) {
        pk_n = g_es[beg];
        const __half* pr = g_Ph + (size_t)(pk_n & 0xFFFFF) * 768;
        yu_n = *(const uint4*)(pr + 256 + d0);
        au_n = *(const uint4*)(pr + 512 + d0);
    }

    for (int i = 0; i < cnt; i++) {
        uint4 yu = yu_n, au = au_n;
        int be = pk_n >> 20;
        if (i + 1 < cnt) {
            pk_n = g_es[beg + i + 1];
            const __half* pr = g_Ph + (size_t)(pk_n & 0xFFFFF) * 768;
            yu_n = *(const uint4*)(pr + 256 + d0);
            au_n = *(const uint4*)(pr + 512 + d0);
        }

        const uint32_t* xp = &xu.x;
        const uint32_t* yp = &yu.x;
        float s = 0.f;
        #pragma unroll
        for (int q = 0; q < 4; q++) {
            float2 fx = __half22float2(*(const __half2*)&xp[q]);
            float2 fy = __half22float2(*(const __half2*)&yp[q]);
            int d = d0 + q * 2;
            float v;
            v = fx.x + fy.x; v = v >= 0.f ? v : 0.2f * v; s += v * sav[d + 0];
            v = fx.y + fy.y; v = v >= 0.f ? v : 0.2f * v; s += v * sav[d + 1];
        }
        s += __shfl_xor_sync(0xffffffffu, s, 1);
        s += __shfl_xor_sync(0xffffffffu, s, 2);

        float raw = s + sbin[be * 8 + hsel];

        float mn    = fmaxf(m, raw);
        float scale = __expf(m - mn);
        float ev    = __expf(raw - mn);
        ssum = ssum * scale + ev;
        m = mn;

        const uint32_t* ap = &au.x;
        #pragma unroll
        for (int q = 0; q < 4; q++) {
            float2 fa = __half22float2(*(const __half2*)&ap[q]);
            accv[q * 2 + 0] = accv[q * 2 + 0] * scale + ev * fa.x;
            accv[q * 2 + 1] = accv[q * 2 + 1] * scale + ev * fa.y;
        }
    }

    float inv = 1.f / (ssum + 1e-16f);
    float4 o0 = make_float4(accv[0] * inv, accv[1] * inv, accv[2] * inv, accv[3] * inv);
    float4 o1 = make_float4(accv[4] * inv, accv[5] * inv, accv[6] * inv, accv[7] * inv);
    float* op = out + (size_t)n * 256 + d0;
    *(float4*)op       = o0;
    *(float4*)(op + 4) = o1;
}

// ---------------------------------------------------------------------------
extern "C" void kernel_launch(void* const* d_in, const int* in_sizes, int n_in,
                              void* d_out, int out_size)
{
    const float* emb      = (const float*)d_in[0];
    const int*   head     = (const int*)  d_in[1];
    const int*   tail     = (const int*)  d_in[2];
    const int*   bins     = (const int*)  d_in[3];
    const float* attn_w   = (const float*)d_in[4];
    const float* proj_b   = (const float*)d_in[5];
    const float* attn_bin = (const float*)d_in[6];
    const float* attn_vec = (const float*)d_in[7];
    const float* aggr_w   = (const float*)d_in[8];
    const float* aggr_b   = (const float*)d_in[9];
    float* out = (float*)d_out;

    int Nn = in_sizes[0] / 256;
    int E  = in_sizes[1];
    int nb = (Nn + 1023) / 1024;

    // launch order keeps GEMM at index 3 (ncu profiles launch #3)
    zero_kernel<<<(Nn + 255) / 256, 256>>>(Nn);                          // 0
    hist_kernel<<<(E + 255) / 256, 256>>>(head, E);                      // 1
    scan_part_kernel<<<nb, 1024>>>(Nn);                                  // 2
    dim3 ggrid((Nn + BM - 1) / BM, 768 / BN);
    gemm_f16_kernel<<<ggrid, 256>>>(emb, attn_w, aggr_w, proj_b, aggr_b, Nn); // 3 <- profiled
    scan_bsum_kernel<<<1, 1024>>>(nb);                                   // 4
    scan_add_kernel<<<(Nn + 255) / 256, 256>>>(Nn, E);                   // 5
    sortscatter_kernel<<<(E + 255) / 256, 256>>>(head, tail, bins, E);   // 6
    node_kernel<<<(Nn * 32 + 255) / 256, 256>>>(attn_vec, attn_bin, out, Nn); // 7
}

// round 10
// speedup vs baseline: 3.5185x; 1.1639x over previous
#include <cuda_runtime.h>
#include <cuda_fp16.h>
#include <cstdint>

#define NMAX 50000
#define EMAX 500000

// Scratch (static device globals -- no allocation allowed)
__device__ __half g_Ph[(size_t)NMAX * 768];   // 0-255: W1*x+b, 256-511: W2*x, 512-767: Wagg*x+b_agg
__device__ __half g_embh[(size_t)NMAX * 256]; // fp16 emb
__device__ __half g_Wh[768 * 256];            // fp16 packed weights (row j = output col j, K contig)
__device__ int    g_hist[NMAX];
__device__ int    g_cnt[NMAX];
__device__ int    g_offs[NMAX + 1];
__device__ int    g_bsum[1024];
__device__ int    g_es[EMAX];                 // packed: tail | bin<<20 (head-sorted)

__device__ __forceinline__ void cp_async16(uint32_t saddr, const void* gptr, int src_size) {
    asm volatile("cp.async.cg.shared.global [%0], [%1], 16, %2;"
                 :: "r"(saddr), "l"(gptr), "r"(src_size));
}
#define CP_COMMIT() asm volatile("cp.async.commit_group;")

__device__ __forceinline__ uint32_t h2_to_u32(__half2 h) {
    union { __half2 h; uint32_t u; } cvt;
    cvt.h = h;
    return cvt.u;
}

// ---------------------------------------------------------------------------
// prepass: fp32 -> fp16
// ---------------------------------------------------------------------------
__global__ void conv_emb_kernel(const float* __restrict__ emb, int n4) {
    int i = blockIdx.x * blockDim.x + threadIdx.x;
    if (i >= n4) return;
    float4 v = ((const float4*)emb)[i];
    uint2 o;
    o.x = h2_to_u32(__floats2half2_rn(v.x, v.y));
    o.y = h2_to_u32(__floats2half2_rn(v.z, v.w));
    ((uint2*)g_embh)[i] = o;
}

__global__ void conv_w_kernel(const float* __restrict__ attn_w,
                              const float* __restrict__ aggr_w) {
    int i = blockIdx.x * blockDim.x + threadIdx.x;   // 0 .. 768*64-1
    if (i >= 768 * 64) return;
    int j  = i >> 6;
    int c4 = (i & 63) << 2;
    const float* src;
    if (j < 256)      src = attn_w + (size_t)j * 512 + c4;
    else if (j < 512) src = attn_w + (size_t)(j - 256) * 512 + 256 + c4;
    else              src = aggr_w + (size_t)(j - 512) * 256 + c4;
    float4 v = *(const float4*)src;
    uint2 o;
    o.x = h2_to_u32(__floats2half2_rn(v.x, v.y));
    o.y = h2_to_u32(__floats2half2_rn(v.z, v.w));
    *(uint2*)&g_Wh[(size_t)j * 256 + c4] = o;
}

// ---------------------------------------------------------------------------
__global__ void zero_kernel(int Nn) {
    int i = blockIdx.x * blockDim.x + threadIdx.x;
    if (i < Nn) { g_hist[i] = 0; g_cnt[i] = 0; }
}

__global__ void hist_kernel(const int* __restrict__ head, int E) {
    int e = blockIdx.x * blockDim.x + threadIdx.x;
    if (e < E) atomicAdd(&g_hist[head[e]], 1);
}

__global__ void scan_part_kernel(int Nn) {
    __shared__ int swarp[32];
    int tid = threadIdx.x, lane = tid & 31, wid = tid >> 5;
    int i = blockIdx.x * 1024 + tid;
    int v = (i < Nn) ? g_hist[i] : 0;
    int incl = v;
    #pragma unroll
    for (int off = 1; off < 32; off <<= 1) {
        int t = __shfl_up_sync(0xffffffffu, incl, off);
        if (lane >= off) incl += t;
    }
    if (lane == 31) swarp[wid] = incl;
    __syncthreads();
    if (wid == 0) {
        int wv = swarp[lane];
        int winc = wv;
        #pragma unroll
        for (int off = 1; off < 32; off <<= 1) {
            int t = __shfl_up_sync(0xffffffffu, winc, off);
            if (lane >= off) winc += t;
        }
        swarp[lane] = winc - wv;
    }
    __syncthreads();
    int excl = swarp[wid] + incl - v;
    if (i < Nn) g_offs[i] = excl;
    if (tid == 1023) g_bsum[blockIdx.x] = excl + v;
}

__global__ void scan_bsum_kernel(int nb) {
    __shared__ int swarp[32];
    int tid = threadIdx.x, lane = tid & 31, wid = tid >> 5;
    int v = (tid < nb) ? g_bsum[tid] : 0;
    int incl = v;
    #pragma unroll
    for (int off = 1; off < 32; off <<= 1) {
        int t = __shfl_up_sync(0xffffffffu, incl, off);
        if (lane >= off) incl += t;
    }
    if (lane == 31) swarp[wid] = incl;
    __syncthreads();
    if (wid == 0) {
        int wv = swarp[lane];
        int winc = wv;
        #pragma unroll
        for (int off = 1; off < 32; off <<= 1) {
            int t = __shfl_up_sync(0xffffffffu, winc, off);
            if (lane >= off) winc += t;
        }
        swarp[lane] = winc - wv;
    }
    __syncthreads();
    if (tid < nb) g_bsum[tid] = swarp[wid] + incl - v;
}

__global__ void scan_add_kernel(int Nn, int E) {
    int i = blockIdx.x * blockDim.x + threadIdx.x;
    if (i < Nn) g_offs[i] += g_bsum[i >> 10];
    if (i == 0) g_offs[Nn] = E;
}

__global__ void sortscatter_kernel(const int* __restrict__ head,
                                   const int* __restrict__ tail,
                                   const int* __restrict__ bins, int E) {
    int e = blockIdx.x * blockDim.x + threadIdx.x;
    if (e >= E) return;
    int h = head[e];
    int p = g_offs[h] + atomicAdd(&g_cnt[h], 1);
    g_es[p] = tail[e] | (bins[e] << 20);
}

// ---------------------------------------------------------------------------
// Fused per-node GEMM, fp16 tensor cores (mma.m16n8k16, fp32 accum).
// fp16 global inputs; cp.async 16B global->smem (2-stage); ldmatrix fragments.
// Block 128x128, BK=32, 256 threads = 8 warps (4x2), warp tile 32x64.
// ---------------------------------------------------------------------------
#define BM 128
#define BN 128
#define BK 32
#define HP 40    // smem row pitch in halfs (32 + 8); 80 B/row

__global__ void __launch_bounds__(256)
gemm_f16_kernel(const float* __restrict__ proj_b,
                const float* __restrict__ aggr_b,
                int Nn)
{
    __shared__ __half As[2][BM * HP];   // 2 x 10240 B
    __shared__ __half Bs[2][BN * HP];   // 2 x 10240 B

    const int m0    = blockIdx.x * BM;
    const int jbase = blockIdx.y * BN;

    const int tid  = threadIdx.x;
    const int lane = tid & 31;
    const int wid  = tid >> 5;
    const int wm   = wid >> 1;          // rows [wm*32, +32)
    const int wn   = wid & 1;           // cols [wn*64, +64)
    const int qrow = lane >> 2;         // groupID 0..7
    const int qcol = lane & 3;          // threadID-in-group 0..3

    const uint32_t sA = (uint32_t)__cvta_generic_to_shared(&As[0][0]);
    const uint32_t sB = (uint32_t)__cvta_generic_to_shared(&Bs[0][0]);
    const uint32_t STAGE = BM * HP * 2; // bytes per stage

    // cp.async mapping: 512 chunks (16B) per operand per stage; 2 per thread
    const int crow = tid >> 1;           // 0..127
    const int cj   = (tid & 1) << 1;     // 16B-chunk pair base: j = cj, cj+1
    const int gm   = m0 + crow;
    const __half* agp = g_embh + (size_t)gm * 256;
    const __half* bgp = g_Wh + (size_t)(jbase + crow) * 256;
    const uint32_t adst = sA + (crow * HP + cj * 8) * 2;
    const uint32_t bdst = sB + (crow * HP + cj * 8) * 2;
    const int asz = gm < Nn ? 16 : 0;

    float acc[2][8][4];
    #pragma unroll
    for (int i = 0; i < 2; i++)
        #pragma unroll
        for (int j = 0; j < 8; j++)
            #pragma unroll
            for (int k = 0; k < 4; k++) acc[i][j][k] = 0.f;

    // prologue: stage 0
    #pragma unroll
    for (int t = 0; t < 2; t++) {
        cp_async16(adst + t * 16, agp + (cj + t) * 8, asz);
        cp_async16(bdst + t * 16, bgp + (cj + t) * 8, 16);
    }
    CP_COMMIT();

    // ldmatrix base addresses (per thread), stage-relative
    const int lb = lane >> 3;   // block 0..3
    const int lr = lane & 7;    // row in block

    for (int it = 0; it < 8; it++) {
        const int st = it & 1;

        if (it < 7) {
            int k0 = (it + 1) * BK;
            uint32_t so = (uint32_t)((st ^ 1) * STAGE);
            #pragma unroll
            for (int t = 0; t < 2; t++) {
                cp_async16(adst + so + t * 16, agp + k0 + (cj + t) * 8, asz);
                cp_async16(bdst + so + t * 16, bgp + k0 + (cj + t) * 8, 16);
            }
            CP_COMMIT();
            asm volatile("cp.async.wait_group 1;");
        } else {
            asm volatile("cp.async.wait_group 0;");
        }
        __syncthreads();   // current stage visible to all warps

        const uint32_t aSt = sA + st * STAGE;
        const uint32_t bSt = sB + st * STAGE;

        #pragma unroll
        for (int ks = 0; ks < 2; ks++) {
            // A fragments: per mf, ldmatrix.x4
            // block b: row_off=(b&1)*8, k_off=(b>>1)*8
            uint32_t a[2][4];
            #pragma unroll
            for (int mf = 0; mf < 2; mf++) {
                int row = wm * 32 + mf * 16 + ((lb & 1) << 3) + lr;
                int kc  = ks * 16 + ((lb >> 1) << 3);
                uint32_t addr = aSt + (row * HP + kc) * 2;
                asm volatile("ldmatrix.sync.aligned.m8n8.x4.shared.b16 {%0,%1,%2,%3}, [%4];"
                             : "=r"(a[mf][0]), "=r"(a[mf][1]), "=r"(a[mf][2]), "=r"(a[mf][3])
                             : "r"(addr));
            }
            // B fragments: 4x ldmatrix.x4, each covers nf pair {2p, 2p+1}
            // block b: n_off=(b>>1)*8, k_off=(b&1)*8
            uint32_t b[8][2];
            #pragma unroll
            for (int p = 0; p < 4; p++) {
                int n  = wn * 64 + p * 16 + ((lb >> 1) << 3) + lr;
                int kc = ks * 16 + ((lb & 1) << 3);
                uint32_t addr = bSt + (n * HP + kc) * 2;
                asm volatile("ldmatrix.sync.aligned.m8n8.x4.shared.b16 {%0,%1,%2,%3}, [%4];"
                             : "=r"(b[2*p][0]), "=r"(b[2*p][1]),
                               "=r"(b[2*p+1][0]), "=r"(b[2*p+1][1])
                             : "r"(addr));
            }
            #pragma unroll
            for (int mf = 0; mf < 2; mf++)
                #pragma unroll
                for (int nf = 0; nf < 8; nf++) {
                    asm volatile(
                        "mma.sync.aligned.m16n8k16.row.col.f32.f16.f16.f32 "
                        "{%0,%1,%2,%3}, {%4,%5,%6,%7}, {%8,%9}, {%0,%1,%2,%3};"
                        : "+f"(acc[mf][nf][0]), "+f"(acc[mf][nf][1]),
                          "+f"(acc[mf][nf][2]), "+f"(acc[mf][nf][3])
                        : "r"(a[mf][0]), "r"(a[mf][1]), "r"(a[mf][2]), "r"(a[mf][3]),
                          "r"(b[nf][0]), "r"(b[nf][1]));
                }
        }
        __syncthreads();   // compute done before next iter's cp.async overwrites
    }

    // epilogue -> fp16 g_Ph
    #pragma unroll
    for (int mf = 0; mf < 2; mf++) {
        #pragma unroll
        for (int nf = 0; nf < 8; nf++) {
            int gc = jbase + wn * 64 + nf * 8 + 2 * qcol;
            float b0 = 0.f, b1 = 0.f;
            if (gc < 256)       { b0 = proj_b[gc];       b1 = proj_b[gc + 1]; }
            else if (gc >= 512) { b0 = aggr_b[gc - 512]; b1 = aggr_b[gc - 511]; }
            int gr0 = m0 + wm * 32 + mf * 16 + qrow;
            int gr1 = gr0 + 8;
            if (gr0 < Nn)
                *(__half2*)&g_Ph[(size_t)gr0 * 768 + gc] =
                    __floats2half2_rn(acc[mf][nf][0] + b0, acc[mf][nf][1] + b1);
            if (gr1 < Nn)
                *(__half2*)&g_Ph[(size_t)gr1 * 768 + gc] =
                    __floats2half2_rn(acc[mf][nf][2] + b0, acc[mf][nf][3] + b1);
        }
    }
}

// ---------------------------------------------------------------------------
// Per-node fused attention + aggregation: one warp per head node.
// ---------------------------------------------------------------------------
__global__ void node_kernel(const float* __restrict__ attn_vec, // 256
                            const float* __restrict__ attn_bin, // 10*8
                            float* __restrict__ out, int Nn)
{
    __shared__ float sav[256];
    __shared__ float sbin[80];
    for (int i = threadIdx.x; i < 256; i += blockDim.x) sav[i] = attn_vec[i];
    for (int i = threadIdx.x; i < 80;  i += blockDim.x) sbin[i] = attn_bin[i];
    __syncthreads();

    int n    = (blockIdx.x * blockDim.x + threadIdx.x) >> 5;
    int lane = threadIdx.x & 31;
    if (n >= Nn) return;

    int beg = g_offs[n];
    int cnt = g_offs[n + 1] - beg;
    const int d0 = lane * 8;
    const int hsel = lane >> 2;

    uint4 xu = *(const uint4*)(g_Ph + (size_t)n * 768 + d0);

    float m = __int_as_float(0xff800000);
    float ssum = 0.f;
    float accv[8];
    #pragma unroll
    for (int q = 0; q < 8; q++) accv[q] = 0.f;

    uint4 yu_n = make_uint4(0,0,0,0), au_n = make_uint4(0,0,0,0);
    int pk_n = 0;
    if (cnt > 0) {
        pk_n = g_es[beg];
        const __half* pr = g_Ph + (size_t)(pk_n & 0xFFFFF) * 768;
        yu_n = *(const uint4*)(pr + 256 + d0);
        au_n = *(const uint4*)(pr + 512 + d0);
    }

    for (int i = 0; i < cnt; i++) {
        uint4 yu = yu_n, au = au_n;
        int be = pk_n >> 20;
        if (i + 1 < cnt) {
            pk_n = g_es[beg + i + 1];
            const __half* pr = g_Ph + (size_t)(pk_n & 0xFFFFF) * 768;
            yu_n = *(const uint4*)(pr + 256 + d0);
            au_n = *(const uint4*)(pr + 512 + d0);
        }

        const uint32_t* xp = &xu.x;
        const uint32_t* yp = &yu.x;
        float s = 0.f;
        #pragma unroll
        for (int q = 0; q < 4; q++) {
            float2 fx = __half22float2(*(const __half2*)&xp[q]);
            float2 fy = __half22float2(*(const __half2*)&yp[q]);
            int d = d0 + q * 2;
            float v;
            v = fx.x + fy.x; v = v >= 0.f ? v : 0.2f * v; s += v * sav[d + 0];
            v = fx.y + fy.y; v = v >= 0.f ? v : 0.2f * v; s += v * sav[d + 1];
        }
        s += __shfl_xor_sync(0xffffffffu, s, 1);
        s += __shfl_xor_sync(0xffffffffu, s, 2);

        float raw = s + sbin[be * 8 + hsel];

        float mn    = fmaxf(m, raw);
        float scale = __expf(m - mn);
        float ev    = __expf(raw - mn);
        ssum = ssum * scale + ev;
        m = mn;

        const uint32_t* ap = &au.x;
        #pragma unroll
        for (int q = 0; q < 4; q++) {
            float2 fa = __half22float2(*(const __half2*)&ap[q]);
            accv[q * 2 + 0] = accv[q * 2 + 0] * scale + ev * fa.x;
            accv[q * 2 + 1] = accv[q * 2 + 1] * scale + ev * fa.y;
        }
    }

    float inv = 1.f / (ssum + 1e-16f);
    float4 o0 = make_float4(accv[0] * inv, accv[1] * inv, accv[2] * inv, accv[3] * inv);
    float4 o1 = make_float4(accv[4] * inv, accv[5] * inv, accv[6] * inv, accv[7] * inv);
    float* op = out + (size_t)n * 256 + d0;
    *(float4*)op       = o0;
    *(float4*)(op + 4) = o1;
}

// ---------------------------------------------------------------------------
extern "C" void kernel_launch(void* const* d_in, const int* in_sizes, int n_in,
                              void* d_out, int out_size)
{
    const float* emb      = (const float*)d_in[0];
    const int*   head     = (const int*)  d_in[1];
    const int*   tail     = (const int*)  d_in[2];
    const int*   bins     = (const int*)  d_in[3];
    const float* attn_w   = (const float*)d_in[4];
    const float* proj_b   = (const float*)d_in[5];
    const float* attn_bin = (const float*)d_in[6];
    const float* attn_vec = (const float*)d_in[7];
    const float* aggr_w   = (const float*)d_in[8];
    const float* aggr_b   = (const float*)d_in[9];
    float* out = (float*)d_out;

    int Nn = in_sizes[0] / 256;
    int E  = in_sizes[1];
    int nb = (Nn + 1023) / 1024;

    // GEMM stays at launch index 3 (ncu profiles launch #3)
    zero_kernel<<<(Nn + 255) / 256, 256>>>(Nn);                           // 0
    conv_emb_kernel<<<(Nn * 64 + 255) / 256, 256>>>(emb, Nn * 64);        // 1
    conv_w_kernel<<<(768 * 64 + 255) / 256, 256>>>(attn_w, aggr_w);       // 2
    dim3 ggrid((Nn + BM - 1) / BM, 768 / BN);
    gemm_f16_kernel<<<ggrid, 256>>>(proj_b, aggr_b, Nn);                  // 3 <- profiled
    hist_kernel<<<(E + 255) / 256, 256>>>(head, E);                       // 4
    scan_part_kernel<<<nb, 1024>>>(Nn);                                   // 5
    scan_bsum_kernel<<<1, 1024>>>(nb);                                    // 6
    scan_add_kernel<<<(Nn + 255) / 256, 256>>>(Nn, E);                    // 7
    sortscatter_kernel<<<(E + 255) / 256, 256>>>(head, tail, bins, E);    // 8
    node_kernel<<<(Nn * 32 + 255) / 256, 256>>>(attn_vec, attn_bin, out, Nn); // 9
}

// round 11
// speedup vs baseline: 3.7123x; 1.0551x over previous
#include <cuda_runtime.h>
#include <cuda_fp16.h>
#include <cstdint>

#define NMAX 50000
#define EMAX 500000

// Scratch (static device globals -- no allocation allowed)
__device__ __half g_Ph[(size_t)NMAX * 768];   // 0-255: W1*x+b, 256-511: W2*x, 512-767: Wagg*x+b_agg
__device__ __half g_embh[(size_t)NMAX * 256]; // fp16 emb
__device__ __half g_Wh[768 * 256];            // fp16 packed weights (row j = output col j, K contig)
__device__ int    g_hist[NMAX];
__device__ int    g_cnt[NMAX];
__device__ int    g_offs[NMAX + 1];
__device__ int    g_bsum[1024];
__device__ int    g_es[EMAX];                 // packed: tail | bin<<20 (head-sorted)

__device__ __forceinline__ void cp_async16(uint32_t saddr, const void* gptr, int src_size) {
    asm volatile("cp.async.cg.shared.global [%0], [%1], 16, %2;"
                 :: "r"(saddr), "l"(gptr), "r"(src_size));
}
#define CP_COMMIT() asm volatile("cp.async.commit_group;")

__device__ __forceinline__ uint32_t h2_to_u32(__half2 h) {
    union { __half2 h; uint32_t u; } cvt;
    cvt.h = h;
    return cvt.u;
}

// ---------------------------------------------------------------------------
// prepass: fp32 -> fp16
// ---------------------------------------------------------------------------
__global__ void conv_emb_kernel(const float* __restrict__ emb, int n4) {
    int i = blockIdx.x * blockDim.x + threadIdx.x;
    if (i >= n4) return;
    float4 v = ((const float4*)emb)[i];
    uint2 o;
    o.x = h2_to_u32(__floats2half2_rn(v.x, v.y));
    o.y = h2_to_u32(__floats2half2_rn(v.z, v.w));
    ((uint2*)g_embh)[i] = o;
}

__global__ void conv_w_kernel(const float* __restrict__ attn_w,
                              const float* __restrict__ aggr_w) {
    int i = blockIdx.x * blockDim.x + threadIdx.x;   // 0 .. 768*64-1
    if (i >= 768 * 64) return;
    int j  = i >> 6;
    int c4 = (i & 63) << 2;
    const float* src;
    if (j < 256)      src = attn_w + (size_t)j * 512 + c4;
    else if (j < 512) src = attn_w + (size_t)(j - 256) * 512 + 256 + c4;
    else              src = aggr_w + (size_t)(j - 512) * 256 + c4;
    float4 v = *(const float4*)src;
    uint2 o;
    o.x = h2_to_u32(__floats2half2_rn(v.x, v.y));
    o.y = h2_to_u32(__floats2half2_rn(v.z, v.w));
    *(uint2*)&g_Wh[(size_t)j * 256 + c4] = o;
}

// ---------------------------------------------------------------------------
__global__ void zero_kernel(int Nn) {
    int i = blockIdx.x * blockDim.x + threadIdx.x;
    if (i < Nn) { g_hist[i] = 0; g_cnt[i] = 0; }
}

__global__ void hist_kernel(const int* __restrict__ head, int E) {
    int e = blockIdx.x * blockDim.x + threadIdx.x;
    if (e < E) atomicAdd(&g_hist[head[e]], 1);
}

__global__ void scan_part_kernel(int Nn) {
    __shared__ int swarp[32];
    int tid = threadIdx.x, lane = tid & 31, wid = tid >> 5;
    int i = blockIdx.x * 1024 + tid;
    int v = (i < Nn) ? g_hist[i] : 0;
    int incl = v;
    #pragma unroll
    for (int off = 1; off < 32; off <<= 1) {
        int t = __shfl_up_sync(0xffffffffu, incl, off);
        if (lane >= off) incl += t;
    }
    if (lane == 31) swarp[wid] = incl;
    __syncthreads();
    if (wid == 0) {
        int wv = swarp[lane];
        int winc = wv;
        #pragma unroll
        for (int off = 1; off < 32; off <<= 1) {
            int t = __shfl_up_sync(0xffffffffu, winc, off);
            if (lane >= off) winc += t;
        }
        swarp[lane] = winc - wv;
    }
    __syncthreads();
    int excl = swarp[wid] + incl - v;
    if (i < Nn) g_offs[i] = excl;
    if (tid == 1023) g_bsum[blockIdx.x] = excl + v;
}

__global__ void scan_bsum_kernel(int nb) {
    __shared__ int swarp[32];
    int tid = threadIdx.x, lane = tid & 31, wid = tid >> 5;
    int v = (tid < nb) ? g_bsum[tid] : 0;
    int incl = v;
    #pragma unroll
    for (int off = 1; off < 32; off <<= 1) {
        int t = __shfl_up_sync(0xffffffffu, incl, off);
        if (lane >= off) incl += t;
    }
    if (lane == 31) swarp[wid] = incl;
    __syncthreads();
    if (wid == 0) {
        int wv = swarp[lane];
        int winc = wv;
        #pragma unroll
        for (int off = 1; off < 32; off <<= 1) {
            int t = __shfl_up_sync(0xffffffffu, winc, off);
            if (lane >= off) winc += t;
        }
        swarp[lane] = winc - wv;
    }
    __syncthreads();
    if (tid < nb) g_bsum[tid] = swarp[wid] + incl - v;
}

__global__ void scan_add_kernel(int Nn, int E) {
    int i = blockIdx.x * blockDim.x + threadIdx.x;
    if (i < Nn) g_offs[i] += g_bsum[i >> 10];
    if (i == 0) g_offs[Nn] = E;
}

__global__ void sortscatter_kernel(const int* __restrict__ head,
                                   const int* __restrict__ tail,
                                   const int* __restrict__ bins, int E) {
    int e = blockIdx.x * blockDim.x + threadIdx.x;
    if (e >= E) return;
    int h = head[e];
    int p = g_offs[h] + atomicAdd(&g_cnt[h], 1);
    g_es[p] = tail[e] | (bins[e] << 20);
}

// ---------------------------------------------------------------------------
// Fused per-node GEMM, fp16 tensor cores (mma.m16n8k16, fp32 accum).
// 4-stage cp.async pipeline, ONE __syncthreads per mainloop iter,
// ldmatrix fragments. Block 128x128, BK=32, 8 warps (4x2), warp tile 32x64.
// ---------------------------------------------------------------------------
#define BM 128
#define BN 128
#define BK 32
#define HP 40    // smem row pitch in halfs (32 + 8); 80 B/row
#define STAGE_B ((BM + BN) * HP * 2)   // 20480 bytes per stage
#define NSTAGE 4
#define GEMM_SMEM (STAGE_B * NSTAGE)   // 81920 bytes

__global__ void __launch_bounds__(256)
gemm_f16_kernel(const float* __restrict__ proj_b,
                const float* __restrict__ aggr_b,
                int Nn)
{
    extern __shared__ __half smh[];

    const int m0    = blockIdx.x * BM;
    const int jbase = blockIdx.y * BN;

    const int tid  = threadIdx.x;
    const int lane = tid & 31;
    const int wid  = tid >> 5;
    const int wm   = wid >> 1;          // rows [wm*32, +32)
    const int wn   = wid & 1;           // cols [wn*64, +64)
    const int qrow = lane >> 2;         // groupID 0..7
    const int qcol = lane & 3;          // threadID-in-group 0..3

    const uint32_t s0 = (uint32_t)__cvta_generic_to_shared(smh);

    // cp.async mapping: 512 chunks (16B) per operand per stage; 2 per thread
    const int crow = tid >> 1;           // 0..127
    const int cj   = (tid & 1) << 1;     // 16B-chunk pair base: j = cj, cj+1
    const int gm   = m0 + crow;
    const __half* agp = g_embh + (size_t)gm * 256;
    const __half* bgp = g_Wh + (size_t)(jbase + crow) * 256;
    const uint32_t adst = s0 + (crow * HP + cj * 8) * 2;
    const uint32_t bdst = s0 + (uint32_t)(BM * HP * 2) + (crow * HP + cj * 8) * 2;
    const int asz = gm < Nn ? 16 : 0;

    float acc[2][8][4];
    #pragma unroll
    for (int i = 0; i < 2; i++)
        #pragma unroll
        for (int j = 0; j < 8; j++)
            #pragma unroll
            for (int k = 0; k < 4; k++) acc[i][j][k] = 0.f;

    // prologue: stages 0,1,2
    #pragma unroll
    for (int s = 0; s < 3; s++) {
        uint32_t so = (uint32_t)(s * STAGE_B);
        int k0 = s * BK;
        #pragma unroll
        for (int t = 0; t < 2; t++) {
            cp_async16(adst + so + t * 16, agp + k0 + (cj + t) * 8, asz);
            cp_async16(bdst + so + t * 16, bgp + k0 + (cj + t) * 8, 16);
        }
        CP_COMMIT();
    }

    const int lb = lane >> 3;   // ldmatrix block 0..3
    const int lr = lane & 7;    // row in block

    #pragma unroll
    for (int it = 0; it < 8; it++) {
        // wait for stage it to complete
        if (it <= 5)      asm volatile("cp.async.wait_group 2;");
        else if (it == 6) asm volatile("cp.async.wait_group 1;");
        else              asm volatile("cp.async.wait_group 0;");
        __syncthreads();   // stage it visible; buffer (it+3)%4 free (read at it-1)

        // issue stage it+3
        if (it < 5) {
            uint32_t so = (uint32_t)(((it + 3) & 3) * STAGE_B);
            int k0 = (it + 3) * BK;
            #pragma unroll
            for (int t = 0; t < 2; t++) {
                cp_async16(adst + so + t * 16, agp + k0 + (cj + t) * 8, asz);
                cp_async16(bdst + so + t * 16, bgp + k0 + (cj + t) * 8, 16);
            }
            CP_COMMIT();
        }

        const uint32_t aSt = s0 + (uint32_t)((it & 3) * STAGE_B);
        const uint32_t bSt = aSt + (uint32_t)(BM * HP * 2);

        #pragma unroll
        for (int ks = 0; ks < 2; ks++) {
            uint32_t a[2][4];
            #pragma unroll
            for (int mf = 0; mf < 2; mf++) {
                int row = wm * 32 + mf * 16 + ((lb & 1) << 3) + lr;
                int kc  = ks * 16 + ((lb >> 1) << 3);
                uint32_t addr = aSt + (row * HP + kc) * 2;
                asm volatile("ldmatrix.sync.aligned.m8n8.x4.shared.b16 {%0,%1,%2,%3}, [%4];"
                             : "=r"(a[mf][0]), "=r"(a[mf][1]), "=r"(a[mf][2]), "=r"(a[mf][3])
                             : "r"(addr));
            }
            uint32_t b[8][2];
            #pragma unroll
            for (int p = 0; p < 4; p++) {
                int n  = wn * 64 + p * 16 + ((lb >> 1) << 3) + lr;
                int kc = ks * 16 + ((lb & 1) << 3);
                uint32_t addr = bSt + (n * HP + kc) * 2;
                asm volatile("ldmatrix.sync.aligned.m8n8.x4.shared.b16 {%0,%1,%2,%3}, [%4];"
                             : "=r"(b[2*p][0]), "=r"(b[2*p][1]),
                               "=r"(b[2*p+1][0]), "=r"(b[2*p+1][1])
                             : "r"(addr));
            }
            #pragma unroll
            for (int mf = 0; mf < 2; mf++)
                #pragma unroll
                for (int nf = 0; nf < 8; nf++) {
                    asm volatile(
                        "mma.sync.aligned.m16n8k16.row.col.f32.f16.f16.f32 "
                        "{%0,%1,%2,%3}, {%4,%5,%6,%7}, {%8,%9}, {%0,%1,%2,%3};"
                        : "+f"(acc[mf][nf][0]), "+f"(acc[mf][nf][1]),
                          "+f"(acc[mf][nf][2]), "+f"(acc[mf][nf][3])
                        : "r"(a[mf][0]), "r"(a[mf][1]), "r"(a[mf][2]), "r"(a[mf][3]),
                          "r"(b[nf][0]), "r"(b[nf][1]));
                }
        }
    }

    // epilogue -> fp16 g_Ph
    #pragma unroll
    for (int mf = 0; mf < 2; mf++) {
        #pragma unroll
        for (int nf = 0; nf < 8; nf++) {
            int gc = jbase + wn * 64 + nf * 8 + 2 * qcol;
            float b0 = 0.f, b1 = 0.f;
            if (gc < 256)       { b0 = proj_b[gc];       b1 = proj_b[gc + 1]; }
            else if (gc >= 512) { b0 = aggr_b[gc - 512]; b1 = aggr_b[gc - 511]; }
            int gr0 = m0 + wm * 32 + mf * 16 + qrow;
            int gr1 = gr0 + 8;
            if (gr0 < Nn)
                *(__half2*)&g_Ph[(size_t)gr0 * 768 + gc] =
                    __floats2half2_rn(acc[mf][nf][0] + b0, acc[mf][nf][1] + b1);
            if (gr1 < Nn)
                *(__half2*)&g_Ph[(size_t)gr1 * 768 + gc] =
                    __floats2half2_rn(acc[mf][nf][2] + b0, acc[mf][nf][3] + b1);
        }
    }
}

// ---------------------------------------------------------------------------
// Per-node fused attention + aggregation: one warp per head node.
// ---------------------------------------------------------------------------
__global__ void node_kernel(const float* __restrict__ attn_vec, // 256
                            const float* __restrict__ attn_bin, // 10*8
                            float* __restrict__ out, int Nn)
{
    __shared__ float sav[256];
    __shared__ float sbin[80];
    for (int i = threadIdx.x; i < 256; i += blockDim.x) sav[i] = attn_vec[i];
    for (int i = threadIdx.x; i < 80;  i += blockDim.x) sbin[i] = attn_bin[i];
    __syncthreads();

    int n    = (blockIdx.x * blockDim.x + threadIdx.x) >> 5;
    int lane = threadIdx.x & 31;
    if (n >= Nn) return;

    int beg = g_offs[n];
    int cnt = g_offs[n + 1] - beg;
    const int d0 = lane * 8;
    const int hsel = lane >> 2;

    uint4 xu = *(const uint4*)(g_Ph + (size_t)n * 768 + d0);

    float m = __int_as_float(0xff800000);
    float ssum = 0.f;
    float accv[8];
    #pragma unroll
    for (int q = 0; q < 8; q++) accv[q] = 0.f;

    uint4 yu_n = make_uint4(0,0,0,0), au_n = make_uint4(0,0,0,0);
    int pk_n = 0;
    if (cnt > 0) {
        pk_n = g_es[beg];
        const __half* pr = g_Ph + (size_t)(pk_n & 0xFFFFF) * 768;
        yu_n = *(const uint4*)(pr + 256 + d0);
        au_n = *(const uint4*)(pr + 512 + d0);
    }

    for (int i = 0; i < cnt; i++) {
        uint4 yu = yu_n, au = au_n;
        int be = pk_n >> 20;
        if (i + 1 < cnt) {
            pk_n = g_es[beg + i + 1];
            const __half* pr = g_Ph + (size_t)(pk_n & 0xFFFFF) * 768;
            yu_n = *(const uint4*)(pr + 256 + d0);
            au_n = *(const uint4*)(pr + 512 + d0);
        }

        const uint32_t* xp = &xu.x;
        const uint32_t* yp = &yu.x;
        float s = 0.f;
        #pragma unroll
        for (int q = 0; q < 4; q++) {
            float2 fx = __half22float2(*(const __half2*)&xp[q]);
            float2 fy = __half22float2(*(const __half2*)&yp[q]);
            int d = d0 + q * 2;
            float v;
            v = fx.x + fy.x; v = v >= 0.f ? v : 0.2f * v; s += v * sav[d + 0];
            v = fx.y + fy.y; v = v >= 0.f ? v : 0.2f * v; s += v * sav[d + 1];
        }
        s += __shfl_xor_sync(0xffffffffu, s, 1);
        s += __shfl_xor_sync(0xffffffffu, s, 2);

        float raw = s + sbin[be * 8 + hsel];

        float mn    = fmaxf(m, raw);
        float scale = __expf(m - mn);
        float ev    = __expf(raw - mn);
        ssum = ssum * scale + ev;
        m = mn;

        const uint32_t* ap = &au.x;
        #pragma unroll
        for (int q = 0; q < 4; q++) {
            float2 fa = __half22float2(*(const __half2*)&ap[q]);
            accv[q * 2 + 0] = accv[q * 2 + 0] * scale + ev * fa.x;
            accv[q * 2 + 1] = accv[q * 2 + 1] * scale + ev * fa.y;
        }
    }

    float inv = 1.f / (ssum + 1e-16f);
    float4 o0 = make_float4(accv[0] * inv, accv[1] * inv, accv[2] * inv, accv[3] * inv);
    float4 o1 = make_float4(accv[4] * inv, accv[5] * inv, accv[6] * inv, accv[7] * inv);
    float* op = out + (size_t)n * 256 + d0;
    *(float4*)op       = o0;
    *(float4*)(op + 4) = o1;
}

// ---------------------------------------------------------------------------
extern "C" void kernel_launch(void* const* d_in, const int* in_sizes, int n_in,
                              void* d_out, int out_size)
{
    const float* emb      = (const float*)d_in[0];
    const int*   head     = (const int*)  d_in[1];
    const int*   tail     = (const int*)  d_in[2];
    const int*   bins     = (const int*)  d_in[3];
    const float* attn_w   = (const float*)d_in[4];
    const float* proj_b   = (const float*)d_in[5];
    const float* attn_bin = (const float*)d_in[6];
    const float* attn_vec = (const float*)d_in[7];
    const float* aggr_w   = (const float*)d_in[8];
    const float* aggr_b   = (const float*)d_in[9];
    float* out = (float*)d_out;

    int Nn = in_sizes[0] / 256;
    int E  = in_sizes[1];
    int nb = (Nn + 1023) / 1024;

    cudaFuncSetAttribute(gemm_f16_kernel,
                         cudaFuncAttributeMaxDynamicSharedMemorySize, GEMM_SMEM);

    // GEMM stays at launch index 3 (ncu profiles launch #3)
    zero_kernel<<<(Nn + 255) / 256, 256>>>(Nn);                           // 0
    conv_emb_kernel<<<(Nn * 64 + 255) / 256, 256>>>(emb, Nn * 64);        // 1
    conv_w_kernel<<<(768 * 64 + 255) / 256, 256>>>(attn_w, aggr_w);       // 2
    dim3 ggrid((Nn + BM - 1) / BM, 768 / BN);
    gemm_f16_kernel<<<ggrid, 256, GEMM_SMEM>>>(proj_b, aggr_b, Nn);       // 3 <- profiled
    hist_kernel<<<(E + 255) / 256, 256>>>(head, E);                       // 4
    scan_part_kernel<<<nb, 1024>>>(Nn);                                   // 5
    scan_bsum_kernel<<<1, 1024>>>(nb);                                    // 6
    scan_add_kernel<<<(Nn + 255) / 256, 256>>>(Nn, E);                    // 7
    sortscatter_kernel<<<(E + 255) / 256, 256>>>(head, tail, bins, E);    // 8
    node_kernel<<<(Nn * 32 + 255) / 256, 256>>>(attn_vec, attn_bin, out, Nn); // 9
}